// round 2
// baseline (speedup 1.0000x reference)
#include <cuda_runtime.h>
#include <cuda_bf16.h>
#include <math.h>

#define N_PANO 50000
#define N_FP   10000
#define HID    128
#define OUT_D  64
#define E_PP   800000
#define E_PF   50000

// ---------------- device scratch (static, no allocation) ----------------
__device__ float g_h[N_PANO * HID];
__device__ float g_hs[N_PANO * HID];
__device__ float g_lin[N_PANO * HID];
__device__ float g_acc[N_PANO * HID];
__device__ float g_es[N_PANO];
__device__ float g_ed[N_PANO];
__device__ float g_edfp[N_FP];
__device__ float g_den[N_PANO];
__device__ float g_wc[704];

#define FMA2(d, a, b) asm("fma.rn.f32x2 %0, %1, %2, %0;" : "+l"(d) : "l"(a), "l"(b))

// ---------------- compose: w = W @ a  (tiny) ----------------
__global__ void compose_kernel(const float* __restrict__ Ws0, const float* __restrict__ as0,
                               const float* __restrict__ Wd0, const float* __restrict__ ad0,
                               const float* __restrict__ Ws1, const float* __restrict__ as1,
                               const float* __restrict__ Wd1, const float* __restrict__ ad1,
                               const float* __restrict__ Wts, const float* __restrict__ ats,
                               const float* __restrict__ Wtd, const float* __restrict__ atd) {
    int b = blockIdx.x, t = threadIdx.x;
    if (b == 0) {
        if (t < 128) {
            float s = 0.f;
            #pragma unroll 8
            for (int n = 0; n < 128; n++) s += Ws0[t * 128 + n] * as0[n];
            g_wc[t] = s;
        } else {
            int i = t - 128; float s = 0.f;
            #pragma unroll 8
            for (int n = 0; n < 128; n++) s += Wd0[i * 128 + n] * ad0[n];
            g_wc[128 + i] = s;
        }
    } else if (b == 1) {
        if (t < 128) {
            float s = 0.f;
            #pragma unroll 8
            for (int n = 0; n < 128; n++) s += Ws1[t * 128 + n] * as1[n];
            g_wc[256 + t] = s;
        } else {
            int i = t - 128; float s = 0.f;
            #pragma unroll 8
            for (int n = 0; n < 128; n++) s += Wd1[i * 128 + n] * ad1[n];
            g_wc[384 + i] = s;
        }
    } else {
        if (t < 128) {
            float s = 0.f;
            #pragma unroll 8
            for (int n = 0; n < 64; n++) s += Wts[t * 64 + n] * ats[n];
            g_wc[512 + t] = s;
        } else if (t < 192) {
            int i = t - 128; float s = 0.f;
            #pragma unroll 8
            for (int n = 0; n < 64; n++) s += Wtd[i * 64 + n] * atd[n];
            g_wc[640 + i] = s;
        }
    }
}

// ---------------- fused dual GEMM: C1 = A@B1, C2 = A@B2 (all [*,128]x[128,128]) ----------------
// f32x2 packed-FMA inner loop; A duplicated in SMEM so LDS.64 yields (a,a).
__global__ void __launch_bounds__(256) dualgemm_kernel(const float* __restrict__ A,
                                                       const float* __restrict__ B1,
                                                       const float* __restrict__ B2,
                                                       float* __restrict__ C1,
                                                       float* __restrict__ C2, int M) {
    __shared__ float2 As[64 * 32];   // 16 KB, (a,a) duplicated pairs
    __shared__ float  Bs1[32 * 128]; // 16 KB
    __shared__ float  Bs2[32 * 128]; // 16 KB
    const int tid = threadIdx.x;
    const int m0 = blockIdx.x * 64;
    const int tx = tid & 15, ty = tid >> 4;

    unsigned long long acc[4][8];
    #pragma unroll
    for (int i = 0; i < 4; i++)
        #pragma unroll
        for (int p = 0; p < 8; p++) acc[i][p] = 0ull;

    #pragma unroll 1
    for (int k0 = 0; k0 < 128; k0 += 32) {
        // A tile: 64 rows x 32 k, duplicated into float2
        #pragma unroll
        for (int l = 0; l < 2; l++) {
            int idx = tid + l * 256;           // 0..511 float4s
            int r = idx >> 3;
            int c = (idx & 7) * 4;
            float4 v = make_float4(0.f, 0.f, 0.f, 0.f);
            if (m0 + r < M) v = *(const float4*)&A[(size_t)(m0 + r) * 128 + k0 + c];
            As[r * 32 + c + 0] = make_float2(v.x, v.x);
            As[r * 32 + c + 1] = make_float2(v.y, v.y);
            As[r * 32 + c + 2] = make_float2(v.z, v.z);
            As[r * 32 + c + 3] = make_float2(v.w, v.w);
        }
        // B tiles: 32 contiguous rows each
        const float4* b1g = (const float4*)(B1 + k0 * 128);
        const float4* b2g = (const float4*)(B2 + k0 * 128);
        #pragma unroll
        for (int l = 0; l < 4; l++) {
            int idx = tid + l * 256;           // 0..1023 float4s
            ((float4*)Bs1)[idx] = b1g[idx];
            ((float4*)Bs2)[idx] = b2g[idx];
        }
        __syncthreads();
        #pragma unroll
        for (int k = 0; k < 32; k++) {
            unsigned long long a0 = *(const unsigned long long*)&As[(ty * 4 + 0) * 32 + k];
            unsigned long long a1 = *(const unsigned long long*)&As[(ty * 4 + 1) * 32 + k];
            unsigned long long a2 = *(const unsigned long long*)&As[(ty * 4 + 2) * 32 + k];
            unsigned long long a3 = *(const unsigned long long*)&As[(ty * 4 + 3) * 32 + k];
            ulonglong2 b1lo = *(const ulonglong2*)&Bs1[k * 128 + tx * 4];
            ulonglong2 b1hi = *(const ulonglong2*)&Bs1[k * 128 + 64 + tx * 4];
            ulonglong2 b2lo = *(const ulonglong2*)&Bs2[k * 128 + tx * 4];
            ulonglong2 b2hi = *(const ulonglong2*)&Bs2[k * 128 + 64 + tx * 4];
            FMA2(acc[0][0], a0, b1lo.x); FMA2(acc[0][1], a0, b1lo.y);
            FMA2(acc[0][2], a0, b1hi.x); FMA2(acc[0][3], a0, b1hi.y);
            FMA2(acc[0][4], a0, b2lo.x); FMA2(acc[0][5], a0, b2lo.y);
            FMA2(acc[0][6], a0, b2hi.x); FMA2(acc[0][7], a0, b2hi.y);
            FMA2(acc[1][0], a1, b1lo.x); FMA2(acc[1][1], a1, b1lo.y);
            FMA2(acc[1][2], a1, b1hi.x); FMA2(acc[1][3], a1, b1hi.y);
            FMA2(acc[1][4], a1, b2lo.x); FMA2(acc[1][5], a1, b2lo.y);
            FMA2(acc[1][6], a1, b2hi.x); FMA2(acc[1][7], a1, b2hi.y);
            FMA2(acc[2][0], a2, b1lo.x); FMA2(acc[2][1], a2, b1lo.y);
            FMA2(acc[2][2], a2, b1hi.x); FMA2(acc[2][3], a2, b1hi.y);
            FMA2(acc[2][4], a2, b2lo.x); FMA2(acc[2][5], a2, b2lo.y);
            FMA2(acc[2][6], a2, b2hi.x); FMA2(acc[2][7], a2, b2hi.y);
            FMA2(acc[3][0], a3, b1lo.x); FMA2(acc[3][1], a3, b1lo.y);
            FMA2(acc[3][2], a3, b1hi.x); FMA2(acc[3][3], a3, b1hi.y);
            FMA2(acc[3][4], a3, b2lo.x); FMA2(acc[3][5], a3, b2lo.y);
            FMA2(acc[3][6], a3, b2hi.x); FMA2(acc[3][7], a3, b2hi.y);
        }
        __syncthreads();
    }
    #pragma unroll
    for (int i = 0; i < 4; i++) {
        int r = m0 + ty * 4 + i;
        if (r < M) {
            *(unsigned long long*)&C1[(size_t)r * 128 + tx * 4]          = acc[i][0];
            *(unsigned long long*)&C1[(size_t)r * 128 + tx * 4 + 2]      = acc[i][1];
            *(unsigned long long*)&C1[(size_t)r * 128 + 64 + tx * 4]     = acc[i][2];
            *(unsigned long long*)&C1[(size_t)r * 128 + 64 + tx * 4 + 2] = acc[i][3];
            *(unsigned long long*)&C2[(size_t)r * 128 + tx * 4]          = acc[i][4];
            *(unsigned long long*)&C2[(size_t)r * 128 + tx * 4 + 2]      = acc[i][5];
            *(unsigned long long*)&C2[(size_t)r * 128 + 64 + tx * 4]     = acc[i][6];
            *(unsigned long long*)&C2[(size_t)r * 128 + 64 + tx * 4 + 2] = acc[i][7];
        }
    }
}

// ---------------- GEMM: C[M,64] = A[M,128] @ B[128,64], f32x2 ----------------
__global__ void __launch_bounds__(256) gemm64_kernel(const float* __restrict__ A,
                                                     const float* __restrict__ B,
                                                     float* __restrict__ C, int M) {
    __shared__ float2 As[64 * 32];   // 16 KB
    __shared__ float  Bs[32 * 64];   // 8 KB
    const int tid = threadIdx.x;
    const int m0 = blockIdx.x * 64;
    const int tx = tid & 15, ty = tid >> 4;

    unsigned long long acc[4][2];
    #pragma unroll
    for (int i = 0; i < 4; i++) { acc[i][0] = 0ull; acc[i][1] = 0ull; }

    #pragma unroll 1
    for (int k0 = 0; k0 < 128; k0 += 32) {
        #pragma unroll
        for (int l = 0; l < 2; l++) {
            int idx = tid + l * 256;
            int r = idx >> 3;
            int c = (idx & 7) * 4;
            float4 v = make_float4(0.f, 0.f, 0.f, 0.f);
            if (m0 + r < M) v = *(const float4*)&A[(size_t)(m0 + r) * 128 + k0 + c];
            As[r * 32 + c + 0] = make_float2(v.x, v.x);
            As[r * 32 + c + 1] = make_float2(v.y, v.y);
            As[r * 32 + c + 2] = make_float2(v.z, v.z);
            As[r * 32 + c + 3] = make_float2(v.w, v.w);
        }
        const float4* bg = (const float4*)(B + k0 * 64);
        #pragma unroll
        for (int l = 0; l < 2; l++) {
            int idx = tid + l * 256;           // 0..511 float4s
            ((float4*)Bs)[idx] = bg[idx];
        }
        __syncthreads();
        #pragma unroll
        for (int k = 0; k < 32; k++) {
            unsigned long long a0 = *(const unsigned long long*)&As[(ty * 4 + 0) * 32 + k];
            unsigned long long a1 = *(const unsigned long long*)&As[(ty * 4 + 1) * 32 + k];
            unsigned long long a2 = *(const unsigned long long*)&As[(ty * 4 + 2) * 32 + k];
            unsigned long long a3 = *(const unsigned long long*)&As[(ty * 4 + 3) * 32 + k];
            ulonglong2 bv = *(const ulonglong2*)&Bs[k * 64 + tx * 4];
            FMA2(acc[0][0], a0, bv.x); FMA2(acc[0][1], a0, bv.y);
            FMA2(acc[1][0], a1, bv.x); FMA2(acc[1][1], a1, bv.y);
            FMA2(acc[2][0], a2, bv.x); FMA2(acc[2][1], a2, bv.y);
            FMA2(acc[3][0], a3, bv.x); FMA2(acc[3][1], a3, bv.y);
        }
        __syncthreads();
    }
    #pragma unroll
    for (int i = 0; i < 4; i++) {
        int r = m0 + ty * 4 + i;
        if (r < M) {
            *(unsigned long long*)&C[(size_t)r * 64 + tx * 4]     = acc[i][0];
            *(unsigned long long*)&C[(size_t)r * 64 + tx * 4 + 2] = acc[i][1];
        }
    }
}

// ---------------- GEMV (two dots per row) + fused zeroing of acc/den ----------------
__global__ void gemv2z_kernel(const float* __restrict__ X, const float* __restrict__ wa,
                              const float* __restrict__ wb,
                              float* __restrict__ ea, float* __restrict__ eb, int M) {
    int gw = (blockIdx.x * blockDim.x + threadIdx.x) >> 5;
    int lane = threadIdx.x & 31;
    if (gw >= M) return;
    // zero the aggregation row + denominator for the upcoming edge pass
    *(float4*)&g_acc[(size_t)gw * 128 + lane * 4] = make_float4(0.f, 0.f, 0.f, 0.f);
    if (lane == 0) g_den[gw] = 0.f;
    float4 x = *(const float4*)&X[(size_t)gw * 128 + lane * 4];
    float4 a = *(const float4*)&wa[lane * 4];
    float4 b = *(const float4*)&wb[lane * 4];
    float sa = x.x * a.x + x.y * a.y + x.z * a.z + x.w * a.w;
    float sb = x.x * b.x + x.y * b.y + x.z * b.z + x.w * b.w;
    #pragma unroll
    for (int o = 16; o; o >>= 1) {
        sa += __shfl_xor_sync(0xFFFFFFFFu, sa, o);
        sb += __shfl_xor_sync(0xFFFFFFFFu, sb, o);
    }
    if (lane == 0) { ea[gw] = sa; eb[gw] = sb; }
}

__global__ void gemv1_128_kernel(const float* __restrict__ X, const float* __restrict__ w,
                                 float* __restrict__ out, int M) {
    int gw = (blockIdx.x * blockDim.x + threadIdx.x) >> 5;
    int lane = threadIdx.x & 31;
    if (gw >= M) return;
    float4 x = *(const float4*)&X[(size_t)gw * 128 + lane * 4];
    float4 a = *(const float4*)&w[lane * 4];
    float s = x.x * a.x + x.y * a.y + x.z * a.z + x.w * a.w;
    #pragma unroll
    for (int o = 16; o; o >>= 1) s += __shfl_xor_sync(0xFFFFFFFFu, s, o);
    if (lane == 0) out[gw] = s;
}

// 64-wide GEMV over x_fp + fused zeroing of fp-side acc/den
__global__ void gemv1_64z_kernel(const float* __restrict__ X, const float* __restrict__ w,
                                 float* __restrict__ out, int M) {
    int gw = (blockIdx.x * blockDim.x + threadIdx.x) >> 5;
    int lane = threadIdx.x & 31;
    if (gw >= M) return;
    *(float2*)&g_acc[(size_t)gw * 64 + lane * 2] = make_float2(0.f, 0.f);
    if (lane == 0) g_den[gw] = 0.f;
    float2 x = *(const float2*)&X[(size_t)gw * 64 + lane * 2];
    float2 a = *(const float2*)&w[lane * 2];
    float s = x.x * a.x + x.y * a.y;
    #pragma unroll
    for (int o = 16; o; o >>= 1) s += __shfl_xor_sync(0xFFFFFFFFu, s, o);
    if (lane == 0) out[gw] = s;
}

// ---------------- edge passes ----------------
__global__ void __launch_bounds__(256) edge_pp_kernel(const int* __restrict__ src,
                                                      const int* __restrict__ dst) {
    int gw = (blockIdx.x * blockDim.x + threadIdx.x) >> 5;
    int lane = threadIdx.x & 31;
    if (gw >= E_PP) return;
    int s = __ldg(&src[gw]);
    int d = __ldg(&dst[gw]);
    float ez = g_es[s] + g_ed[d];
    float e = ez > 0.f ? ez : 0.2f * ez;
    float ex = __expf(e);
    float4 h = *(const float4*)&g_hs[(size_t)s * 128 + lane * 4];
    float* p = &g_acc[(size_t)d * 128 + lane * 4];
    asm volatile("red.global.add.v4.f32 [%0], {%1,%2,%3,%4};"
                 :: "l"(p), "f"(h.x * ex), "f"(h.y * ex), "f"(h.z * ex), "f"(h.w * ex)
                 : "memory");
    if (lane == 0) atomicAdd(&g_den[d], ex);
}

__global__ void __launch_bounds__(256) edge_pf_kernel(const int* __restrict__ src,
                                                      const int* __restrict__ dst) {
    int gw = (blockIdx.x * blockDim.x + threadIdx.x) >> 5;
    int lane = threadIdx.x & 31;
    if (gw >= E_PF) return;
    int s = __ldg(&src[gw]);
    int d = __ldg(&dst[gw]);
    float ez = g_es[s] + g_edfp[d];
    float e = ez > 0.f ? ez : 0.2f * ez;
    float ex = __expf(e);
    float2 h = *(const float2*)&g_hs[(size_t)s * 64 + lane * 2];
    float* p = &g_acc[(size_t)d * 64 + lane * 2];
    asm volatile("red.global.add.v2.f32 [%0], {%1,%2};"
                 :: "l"(p), "f"(h.x * ex), "f"(h.y * ex)
                 : "memory");
    if (lane == 0) atomicAdd(&g_den[d], ex);
}

// ---------------- finalize ----------------
__global__ void finalize_layer_kernel(const float* __restrict__ b, const float* __restrict__ Lb) {
    int i = blockIdx.x * blockDim.x + threadIdx.x;   // 1,600,000 float4s
    int row = i >> 5;
    int c4 = (i & 31) * 4;
    float den = g_den[row];
    float inv = den > 0.f ? 1.f / den : 0.f;
    float4 a = ((const float4*)g_acc)[i];
    float4 l = ((const float4*)g_lin)[i];
    float4 bb = *(const float4*)&b[c4];
    float4 lb = *(const float4*)&Lb[c4];
    float4 r;
    r.x = fmaxf(a.x * inv + bb.x + l.x + lb.x, 0.f);
    r.y = fmaxf(a.y * inv + bb.y + l.y + lb.y, 0.f);
    r.z = fmaxf(a.z * inv + bb.z + l.z + lb.z, 0.f);
    r.w = fmaxf(a.w * inv + bb.w + l.w + lb.w, 0.f);
    ((float4*)g_h)[i] = r;
}

__global__ void final_fp_kernel(const float* __restrict__ bt, float* __restrict__ out) {
    int i = blockIdx.x * blockDim.x + threadIdx.x;   // 160,000 float4s
    int row = i >> 4;
    int c4 = (i & 15) * 4;
    float den = g_den[row];
    float inv = den > 0.f ? 1.f / den : 0.f;
    float4 a = ((const float4*)g_acc)[i];
    float4 bb = *(const float4*)&bt[c4];
    float4 r;
    r.x = a.x * inv + bb.x;
    r.y = a.y * inv + bb.y;
    r.z = a.z * inv + bb.z;
    r.w = a.w * inv + bb.w;
    ((float4*)out)[i] = r;
}

// ---------------- launch ----------------
extern "C" void kernel_launch(void* const* d_in, const int* in_sizes, int n_in,
                              void* d_out, int out_size) {
    const float* x_pano = (const float*)d_in[0];
    const float* x_fp   = (const float*)d_in[1];
    const float* Ws0 = (const float*)d_in[2];
    const float* Wd0 = (const float*)d_in[3];
    const float* as0 = (const float*)d_in[4];
    const float* ad0 = (const float*)d_in[5];
    const float* b0  = (const float*)d_in[6];
    const float* Lw0 = (const float*)d_in[7];
    const float* Lb0 = (const float*)d_in[8];
    const float* Ws1 = (const float*)d_in[9];
    const float* Wd1 = (const float*)d_in[10];
    const float* as1 = (const float*)d_in[11];
    const float* ad1 = (const float*)d_in[12];
    const float* b1  = (const float*)d_in[13];
    const float* Lw1 = (const float*)d_in[14];
    const float* Lb1 = (const float*)d_in[15];
    const float* Wts = (const float*)d_in[16];
    const float* Wtd = (const float*)d_in[17];
    const float* ats = (const float*)d_in[18];
    const float* atd = (const float*)d_in[19];
    const float* bt  = (const float*)d_in[20];
    const int* edge_pp = (const int*)d_in[21];
    const int* pf_src  = (const int*)d_in[22];
    const int* pf_dst  = (const int*)d_in[23];
    const int* pp_src = edge_pp;
    const int* pp_dst = edge_pp + E_PP;

    float *p_h, *p_hs, *p_lin, *p_es, *p_ed, *p_edfp, *p_wc;
    cudaGetSymbolAddress((void**)&p_h,   g_h);
    cudaGetSymbolAddress((void**)&p_hs,  g_hs);
    cudaGetSymbolAddress((void**)&p_lin, g_lin);
    cudaGetSymbolAddress((void**)&p_es,  g_es);
    cudaGetSymbolAddress((void**)&p_ed,  g_ed);
    cudaGetSymbolAddress((void**)&p_edfp, g_edfp);
    cudaGetSymbolAddress((void**)&p_wc,  g_wc);

    const int GEMM_BLKS = (N_PANO + 63) / 64;   // 782

    compose_kernel<<<3, 256>>>(Ws0, as0, Wd0, ad0, Ws1, as1, Wd1, ad1, Wts, ats, Wtd, atd);

    // ---- layer 0 ----
    dualgemm_kernel<<<GEMM_BLKS, 256>>>(x_pano, Ws0, Lw0, p_hs, p_lin, N_PANO);
    gemv2z_kernel<<<6250, 256>>>(x_pano, p_wc + 0, p_wc + 128, p_es, p_ed, N_PANO);
    edge_pp_kernel<<<100000, 256>>>(pp_src, pp_dst);
    finalize_layer_kernel<<<6250, 256>>>(b0, Lb0);

    // ---- layer 1 ----
    dualgemm_kernel<<<GEMM_BLKS, 256>>>(p_h, Ws1, Lw1, p_hs, p_lin, N_PANO);
    gemv2z_kernel<<<6250, 256>>>(p_h, p_wc + 256, p_wc + 384, p_es, p_ed, N_PANO);
    edge_pp_kernel<<<100000, 256>>>(pp_src, pp_dst);
    finalize_layer_kernel<<<6250, 256>>>(b1, Lb1);

    // ---- translate pano -> footprint ----
    gemm64_kernel<<<GEMM_BLKS, 256>>>(p_h, Wts, p_hs, N_PANO);
    gemv1_128_kernel<<<6250, 256>>>(p_h, p_wc + 512, p_es, N_PANO);
    gemv1_64z_kernel<<<1250, 256>>>(x_fp, p_wc + 640, p_edfp, N_FP);
    edge_pf_kernel<<<6250, 256>>>(pf_src, pf_dst);
    final_fp_kernel<<<625, 256>>>(bt, (float*)d_out);
}

// round 3
// speedup vs baseline: 1.0897x; 1.0897x over previous
#include <cuda_runtime.h>
#include <cuda_bf16.h>
#include <math.h>

#define N_PANO 50000
#define N_FP   10000
#define HID    128
#define OUT_D  64
#define E_PP   800000
#define E_PF   50000

// ---------------- device scratch (static, no allocation) ----------------
__device__ float g_h[N_PANO * HID];
__device__ float g_hs[N_PANO * HID];
__device__ float g_lin[N_PANO * HID];
__device__ float g_es[N_PANO];
__device__ float g_ed[N_PANO];
__device__ float g_edfp[N_FP];
__device__ float g_wc[704];
// CSR build
__device__ int g_cnt[N_PANO];
__device__ int g_off[N_PANO + 1];
__device__ int g_cur[N_PANO];
__device__ int g_srt[E_PP];
__device__ int g_cnt_fp[N_FP];
__device__ int g_off_fp[N_FP + 1];
__device__ int g_cur_fp[N_FP];
__device__ int g_srt_fp[E_PF];

#define FMA2(d, a, b) asm("fma.rn.f32x2 %0, %1, %2, %0;" : "+l"(d) : "l"(a), "l"(b))

// ---------------- compose: w = W @ a  (tiny) ----------------
__global__ void compose_kernel(const float* __restrict__ Ws0, const float* __restrict__ as0,
                               const float* __restrict__ Wd0, const float* __restrict__ ad0,
                               const float* __restrict__ Ws1, const float* __restrict__ as1,
                               const float* __restrict__ Wd1, const float* __restrict__ ad1,
                               const float* __restrict__ Wts, const float* __restrict__ ats,
                               const float* __restrict__ Wtd, const float* __restrict__ atd) {
    int b = blockIdx.x, t = threadIdx.x;
    if (b == 0) {
        if (t < 128) {
            float s = 0.f;
            #pragma unroll 8
            for (int n = 0; n < 128; n++) s += Ws0[t * 128 + n] * as0[n];
            g_wc[t] = s;
        } else {
            int i = t - 128; float s = 0.f;
            #pragma unroll 8
            for (int n = 0; n < 128; n++) s += Wd0[i * 128 + n] * ad0[n];
            g_wc[128 + i] = s;
        }
    } else if (b == 1) {
        if (t < 128) {
            float s = 0.f;
            #pragma unroll 8
            for (int n = 0; n < 128; n++) s += Ws1[t * 128 + n] * as1[n];
            g_wc[256 + t] = s;
        } else {
            int i = t - 128; float s = 0.f;
            #pragma unroll 8
            for (int n = 0; n < 128; n++) s += Wd1[i * 128 + n] * ad1[n];
            g_wc[384 + i] = s;
        }
    } else {
        if (t < 128) {
            float s = 0.f;
            #pragma unroll 8
            for (int n = 0; n < 64; n++) s += Wts[t * 64 + n] * ats[n];
            g_wc[512 + t] = s;
        } else if (t < 192) {
            int i = t - 128; float s = 0.f;
            #pragma unroll 8
            for (int n = 0; n < 64; n++) s += Wtd[i * 64 + n] * atd[n];
            g_wc[640 + i] = s;
        }
    }
}

// ---------------- CSR build kernels ----------------
__global__ void zero_cnt_kernel() {
    int i = blockIdx.x * blockDim.x + threadIdx.x;
    if (i < N_PANO) g_cnt[i] = 0;
    else if (i < N_PANO + N_FP) g_cnt_fp[i - N_PANO] = 0;
}

__global__ void hist_kernel(const int* __restrict__ dst_pp, const int* __restrict__ dst_pf) {
    int i = blockIdx.x * blockDim.x + threadIdx.x;
    if (i < E_PP) atomicAdd(&g_cnt[dst_pp[i]], 1);
    else if (i < E_PP + E_PF) atomicAdd(&g_cnt_fp[dst_pf[i - E_PP]], 1);
}

// exclusive scan: block 0 -> pp (50000), block 1 -> fp (10000)
__global__ void __launch_bounds__(1024) scan_kernel() {
    __shared__ int totals[1024];
    const int N = (blockIdx.x == 0) ? N_PANO : N_FP;
    int* cnt = (blockIdx.x == 0) ? g_cnt : g_cnt_fp;
    int* off = (blockIdx.x == 0) ? g_off : g_off_fp;
    int* cur = (blockIdx.x == 0) ? g_cur : g_cur_fp;
    int t = threadIdx.x;
    int C = (N + 1023) / 1024;
    int lo = t * C;
    int hi = lo + C; if (hi > N) hi = N; if (lo > N) lo = N;
    int sum = 0;
    for (int i = lo; i < hi; i++) sum += cnt[i];
    totals[t] = sum;
    __syncthreads();
    // Hillis-Steele inclusive scan over totals
    #pragma unroll
    for (int o = 1; o < 1024; o <<= 1) {
        int v = (t >= o) ? totals[t - o] : 0;
        __syncthreads();
        totals[t] += v;
        __syncthreads();
    }
    int run = (t == 0) ? 0 : totals[t - 1];
    for (int i = lo; i < hi; i++) {
        off[i] = run; cur[i] = run;
        run += cnt[i];
    }
    if (hi == N) off[N] = run;
}

__global__ void scatter_kernel(const int* __restrict__ src_pp, const int* __restrict__ dst_pp,
                               const int* __restrict__ src_pf, const int* __restrict__ dst_pf) {
    int i = blockIdx.x * blockDim.x + threadIdx.x;
    if (i < E_PP) {
        int pos = atomicAdd(&g_cur[dst_pp[i]], 1);
        g_srt[pos] = src_pp[i];
    } else if (i < E_PP + E_PF) {
        int j = i - E_PP;
        int pos = atomicAdd(&g_cur_fp[dst_pf[j]], 1);
        g_srt_fp[pos] = src_pf[j];
    }
}

// ---------------- fused dual GEMM: C1 = A@B1, C2 = A@B2 ----------------
__global__ void __launch_bounds__(256) dualgemm_kernel(const float* __restrict__ A,
                                                       const float* __restrict__ B1,
                                                       const float* __restrict__ B2,
                                                       float* __restrict__ C1,
                                                       float* __restrict__ C2, int M) {
    __shared__ float2 As[64 * 32];
    __shared__ float  Bs1[32 * 128];
    __shared__ float  Bs2[32 * 128];
    const int tid = threadIdx.x;
    const int m0 = blockIdx.x * 64;
    const int tx = tid & 15, ty = tid >> 4;

    unsigned long long acc[4][8];
    #pragma unroll
    for (int i = 0; i < 4; i++)
        #pragma unroll
        for (int p = 0; p < 8; p++) acc[i][p] = 0ull;

    #pragma unroll 1
    for (int k0 = 0; k0 < 128; k0 += 32) {
        #pragma unroll
        for (int l = 0; l < 2; l++) {
            int idx = tid + l * 256;
            int r = idx >> 3;
            int c = (idx & 7) * 4;
            float4 v = make_float4(0.f, 0.f, 0.f, 0.f);
            if (m0 + r < M) v = *(const float4*)&A[(size_t)(m0 + r) * 128 + k0 + c];
            As[r * 32 + c + 0] = make_float2(v.x, v.x);
            As[r * 32 + c + 1] = make_float2(v.y, v.y);
            As[r * 32 + c + 2] = make_float2(v.z, v.z);
            As[r * 32 + c + 3] = make_float2(v.w, v.w);
        }
        const float4* b1g = (const float4*)(B1 + k0 * 128);
        const float4* b2g = (const float4*)(B2 + k0 * 128);
        #pragma unroll
        for (int l = 0; l < 4; l++) {
            int idx = tid + l * 256;
            ((float4*)Bs1)[idx] = b1g[idx];
            ((float4*)Bs2)[idx] = b2g[idx];
        }
        __syncthreads();
        #pragma unroll
        for (int k = 0; k < 32; k++) {
            unsigned long long a0 = *(const unsigned long long*)&As[(ty * 4 + 0) * 32 + k];
            unsigned long long a1 = *(const unsigned long long*)&As[(ty * 4 + 1) * 32 + k];
            unsigned long long a2 = *(const unsigned long long*)&As[(ty * 4 + 2) * 32 + k];
            unsigned long long a3 = *(const unsigned long long*)&As[(ty * 4 + 3) * 32 + k];
            ulonglong2 b1lo = *(const ulonglong2*)&Bs1[k * 128 + tx * 4];
            ulonglong2 b1hi = *(const ulonglong2*)&Bs1[k * 128 + 64 + tx * 4];
            ulonglong2 b2lo = *(const ulonglong2*)&Bs2[k * 128 + tx * 4];
            ulonglong2 b2hi = *(const ulonglong2*)&Bs2[k * 128 + 64 + tx * 4];
            FMA2(acc[0][0], a0, b1lo.x); FMA2(acc[0][1], a0, b1lo.y);
            FMA2(acc[0][2], a0, b1hi.x); FMA2(acc[0][3], a0, b1hi.y);
            FMA2(acc[0][4], a0, b2lo.x); FMA2(acc[0][5], a0, b2lo.y);
            FMA2(acc[0][6], a0, b2hi.x); FMA2(acc[0][7], a0, b2hi.y);
            FMA2(acc[1][0], a1, b1lo.x); FMA2(acc[1][1], a1, b1lo.y);
            FMA2(acc[1][2], a1, b1hi.x); FMA2(acc[1][3], a1, b1hi.y);
            FMA2(acc[1][4], a1, b2lo.x); FMA2(acc[1][5], a1, b2lo.y);
            FMA2(acc[1][6], a1, b2hi.x); FMA2(acc[1][7], a1, b2hi.y);
            FMA2(acc[2][0], a2, b1lo.x); FMA2(acc[2][1], a2, b1lo.y);
            FMA2(acc[2][2], a2, b1hi.x); FMA2(acc[2][3], a2, b1hi.y);
            FMA2(acc[2][4], a2, b2lo.x); FMA2(acc[2][5], a2, b2lo.y);
            FMA2(acc[2][6], a2, b2hi.x); FMA2(acc[2][7], a2, b2hi.y);
            FMA2(acc[3][0], a3, b1lo.x); FMA2(acc[3][1], a3, b1lo.y);
            FMA2(acc[3][2], a3, b1hi.x); FMA2(acc[3][3], a3, b1hi.y);
            FMA2(acc[3][4], a3, b2lo.x); FMA2(acc[3][5], a3, b2lo.y);
            FMA2(acc[3][6], a3, b2hi.x); FMA2(acc[3][7], a3, b2hi.y);
        }
        __syncthreads();
    }
    #pragma unroll
    for (int i = 0; i < 4; i++) {
        int r = m0 + ty * 4 + i;
        if (r < M) {
            *(unsigned long long*)&C1[(size_t)r * 128 + tx * 4]          = acc[i][0];
            *(unsigned long long*)&C1[(size_t)r * 128 + tx * 4 + 2]      = acc[i][1];
            *(unsigned long long*)&C1[(size_t)r * 128 + 64 + tx * 4]     = acc[i][2];
            *(unsigned long long*)&C1[(size_t)r * 128 + 64 + tx * 4 + 2] = acc[i][3];
            *(unsigned long long*)&C2[(size_t)r * 128 + tx * 4]          = acc[i][4];
            *(unsigned long long*)&C2[(size_t)r * 128 + tx * 4 + 2]      = acc[i][5];
            *(unsigned long long*)&C2[(size_t)r * 128 + 64 + tx * 4]     = acc[i][6];
            *(unsigned long long*)&C2[(size_t)r * 128 + 64 + tx * 4 + 2] = acc[i][7];
        }
    }
}

// ---------------- GEMM: C[M,64] = A[M,128] @ B[128,64] ----------------
__global__ void __launch_bounds__(256) gemm64_kernel(const float* __restrict__ A,
                                                     const float* __restrict__ B,
                                                     float* __restrict__ C, int M) {
    __shared__ float2 As[64 * 32];
    __shared__ float  Bs[32 * 64];
    const int tid = threadIdx.x;
    const int m0 = blockIdx.x * 64;
    const int tx = tid & 15, ty = tid >> 4;

    unsigned long long acc[4][2];
    #pragma unroll
    for (int i = 0; i < 4; i++) { acc[i][0] = 0ull; acc[i][1] = 0ull; }

    #pragma unroll 1
    for (int k0 = 0; k0 < 128; k0 += 32) {
        #pragma unroll
        for (int l = 0; l < 2; l++) {
            int idx = tid + l * 256;
            int r = idx >> 3;
            int c = (idx & 7) * 4;
            float4 v = make_float4(0.f, 0.f, 0.f, 0.f);
            if (m0 + r < M) v = *(const float4*)&A[(size_t)(m0 + r) * 128 + k0 + c];
            As[r * 32 + c + 0] = make_float2(v.x, v.x);
            As[r * 32 + c + 1] = make_float2(v.y, v.y);
            As[r * 32 + c + 2] = make_float2(v.z, v.z);
            As[r * 32 + c + 3] = make_float2(v.w, v.w);
        }
        const float4* bg = (const float4*)(B + k0 * 64);
        #pragma unroll
        for (int l = 0; l < 2; l++) {
            int idx = tid + l * 256;
            ((float4*)Bs)[idx] = bg[idx];
        }
        __syncthreads();
        #pragma unroll
        for (int k = 0; k < 32; k++) {
            unsigned long long a0 = *(const unsigned long long*)&As[(ty * 4 + 0) * 32 + k];
            unsigned long long a1 = *(const unsigned long long*)&As[(ty * 4 + 1) * 32 + k];
            unsigned long long a2 = *(const unsigned long long*)&As[(ty * 4 + 2) * 32 + k];
            unsigned long long a3 = *(const unsigned long long*)&As[(ty * 4 + 3) * 32 + k];
            ulonglong2 bv = *(const ulonglong2*)&Bs[k * 64 + tx * 4];
            FMA2(acc[0][0], a0, bv.x); FMA2(acc[0][1], a0, bv.y);
            FMA2(acc[1][0], a1, bv.x); FMA2(acc[1][1], a1, bv.y);
            FMA2(acc[2][0], a2, bv.x); FMA2(acc[2][1], a2, bv.y);
            FMA2(acc[3][0], a3, bv.x); FMA2(acc[3][1], a3, bv.y);
        }
        __syncthreads();
    }
    #pragma unroll
    for (int i = 0; i < 4; i++) {
        int r = m0 + ty * 4 + i;
        if (r < M) {
            *(unsigned long long*)&C[(size_t)r * 64 + tx * 4]     = acc[i][0];
            *(unsigned long long*)&C[(size_t)r * 64 + tx * 4 + 2] = acc[i][1];
        }
    }
}

// ---------------- GEMVs ----------------
__global__ void gemv2_kernel(const float* __restrict__ X, const float* __restrict__ wa,
                             const float* __restrict__ wb,
                             float* __restrict__ ea, float* __restrict__ eb, int M) {
    int gw = (blockIdx.x * blockDim.x + threadIdx.x) >> 5;
    int lane = threadIdx.x & 31;
    if (gw >= M) return;
    float4 x = *(const float4*)&X[(size_t)gw * 128 + lane * 4];
    float4 a = *(const float4*)&wa[lane * 4];
    float4 b = *(const float4*)&wb[lane * 4];
    float sa = x.x * a.x + x.y * a.y + x.z * a.z + x.w * a.w;
    float sb = x.x * b.x + x.y * b.y + x.z * b.z + x.w * b.w;
    #pragma unroll
    for (int o = 16; o; o >>= 1) {
        sa += __shfl_xor_sync(0xFFFFFFFFu, sa, o);
        sb += __shfl_xor_sync(0xFFFFFFFFu, sb, o);
    }
    if (lane == 0) { ea[gw] = sa; eb[gw] = sb; }
}

__global__ void gemv1_128_kernel(const float* __restrict__ X, const float* __restrict__ w,
                                 float* __restrict__ out, int M) {
    int gw = (blockIdx.x * blockDim.x + threadIdx.x) >> 5;
    int lane = threadIdx.x & 31;
    if (gw >= M) return;
    float4 x = *(const float4*)&X[(size_t)gw * 128 + lane * 4];
    float4 a = *(const float4*)&w[lane * 4];
    float s = x.x * a.x + x.y * a.y + x.z * a.z + x.w * a.w;
    #pragma unroll
    for (int o = 16; o; o >>= 1) s += __shfl_xor_sync(0xFFFFFFFFu, s, o);
    if (lane == 0) out[gw] = s;
}

__global__ void gemv1_64_kernel(const float* __restrict__ X, const float* __restrict__ w,
                                float* __restrict__ out, int M) {
    int gw = (blockIdx.x * blockDim.x + threadIdx.x) >> 5;
    int lane = threadIdx.x & 31;
    if (gw >= M) return;
    float2 x = *(const float2*)&X[(size_t)gw * 64 + lane * 2];
    float2 a = *(const float2*)&w[lane * 2];
    float s = x.x * a.x + x.y * a.y;
    #pragma unroll
    for (int o = 16; o; o >>= 1) s += __shfl_xor_sync(0xFFFFFFFFu, s, o);
    if (lane == 0) out[gw] = s;
}

// ---------------- CSR aggregation + fused finalize (pano layer) ----------------
// one warp per dst node; gathers hs rows, softmax-weighted sum in registers,
// then h = relu(conv + b + lin + Lb) written directly.
__global__ void __launch_bounds__(256) agg_pp_kernel(const float* __restrict__ b,
                                                     const float* __restrict__ Lb) {
    int gw = (blockIdx.x * blockDim.x + threadIdx.x) >> 5;
    int lane = threadIdx.x & 31;
    if (gw >= N_PANO) return;
    int start = g_off[gw];
    int end   = g_off[gw + 1];
    float edd = g_ed[gw];
    float4 acc = make_float4(0.f, 0.f, 0.f, 0.f);
    float exsum = 0.f;
    for (int base = start; base < end; base += 32) {
        int m = end - base; if (m > 32) m = 32;
        int s = 0; float ex = 0.f;
        if (lane < m) {
            s = g_srt[base + lane];
            float ez = g_es[s] + edd;
            float e = ez > 0.f ? ez : 0.2f * ez;
            ex = __expf(e);
        }
        exsum += ex;
        for (int j = 0; j < m; j++) {
            int sj   = __shfl_sync(0xFFFFFFFFu, s, j);
            float xj = __shfl_sync(0xFFFFFFFFu, ex, j);
            float4 h = *(const float4*)&g_hs[(size_t)sj * 128 + lane * 4];
            acc.x += h.x * xj; acc.y += h.y * xj;
            acc.z += h.z * xj; acc.w += h.w * xj;
        }
    }
    #pragma unroll
    for (int o = 16; o; o >>= 1) exsum += __shfl_xor_sync(0xFFFFFFFFu, exsum, o);
    float inv = exsum > 0.f ? 1.f / exsum : 0.f;
    float4 l  = *(const float4*)&g_lin[(size_t)gw * 128 + lane * 4];
    float4 bb = *(const float4*)&b[lane * 4];
    float4 lb = *(const float4*)&Lb[lane * 4];
    float4 r;
    r.x = fmaxf(acc.x * inv + bb.x + l.x + lb.x, 0.f);
    r.y = fmaxf(acc.y * inv + bb.y + l.y + lb.y, 0.f);
    r.z = fmaxf(acc.z * inv + bb.z + l.z + lb.z, 0.f);
    r.w = fmaxf(acc.w * inv + bb.w + l.w + lb.w, 0.f);
    *(float4*)&g_h[(size_t)gw * 128 + lane * 4] = r;
}

// ---------------- CSR aggregation (translate) -> d_out ----------------
__global__ void __launch_bounds__(256) agg_pf_kernel(const float* __restrict__ bt,
                                                     float* __restrict__ out) {
    int gw = (blockIdx.x * blockDim.x + threadIdx.x) >> 5;
    int lane = threadIdx.x & 31;
    if (gw >= N_FP) return;
    int start = g_off_fp[gw];
    int end   = g_off_fp[gw + 1];
    float edd = g_edfp[gw];
    float2 acc = make_float2(0.f, 0.f);
    float exsum = 0.f;
    for (int base = start; base < end; base += 32) {
        int m = end - base; if (m > 32) m = 32;
        int s = 0; float ex = 0.f;
        if (lane < m) {
            s = g_srt_fp[base + lane];
            float ez = g_es[s] + edd;
            float e = ez > 0.f ? ez : 0.2f * ez;
            ex = __expf(e);
        }
        exsum += ex;
        for (int j = 0; j < m; j++) {
            int sj   = __shfl_sync(0xFFFFFFFFu, s, j);
            float xj = __shfl_sync(0xFFFFFFFFu, ex, j);
            float2 h = *(const float2*)&g_hs[(size_t)sj * 64 + lane * 2];
            acc.x += h.x * xj; acc.y += h.y * xj;
        }
    }
    #pragma unroll
    for (int o = 16; o; o >>= 1) exsum += __shfl_xor_sync(0xFFFFFFFFu, exsum, o);
    float inv = exsum > 0.f ? 1.f / exsum : 0.f;
    float2 bb = *(const float2*)&bt[lane * 2];
    float2 r;
    r.x = acc.x * inv + bb.x;
    r.y = acc.y * inv + bb.y;
    *(float2*)&out[(size_t)gw * 64 + lane * 2] = r;
}

// ---------------- launch ----------------
extern "C" void kernel_launch(void* const* d_in, const int* in_sizes, int n_in,
                              void* d_out, int out_size) {
    const float* x_pano = (const float*)d_in[0];
    const float* x_fp   = (const float*)d_in[1];
    const float* Ws0 = (const float*)d_in[2];
    const float* Wd0 = (const float*)d_in[3];
    const float* as0 = (const float*)d_in[4];
    const float* ad0 = (const float*)d_in[5];
    const float* b0  = (const float*)d_in[6];
    const float* Lw0 = (const float*)d_in[7];
    const float* Lb0 = (const float*)d_in[8];
    const float* Ws1 = (const float*)d_in[9];
    const float* Wd1 = (const float*)d_in[10];
    const float* as1 = (const float*)d_in[11];
    const float* ad1 = (const float*)d_in[12];
    const float* b1  = (const float*)d_in[13];
    const float* Lw1 = (const float*)d_in[14];
    const float* Lb1 = (const float*)d_in[15];
    const float* Wts = (const float*)d_in[16];
    const float* Wtd = (const float*)d_in[17];
    const float* ats = (const float*)d_in[18];
    const float* atd = (const float*)d_in[19];
    const float* bt  = (const float*)d_in[20];
    const int* edge_pp = (const int*)d_in[21];
    const int* pf_src  = (const int*)d_in[22];
    const int* pf_dst  = (const int*)d_in[23];
    const int* pp_src = edge_pp;
    const int* pp_dst = edge_pp + E_PP;

    float *p_h, *p_hs, *p_lin, *p_es, *p_ed, *p_edfp, *p_wc;
    cudaGetSymbolAddress((void**)&p_h,   g_h);
    cudaGetSymbolAddress((void**)&p_hs,  g_hs);
    cudaGetSymbolAddress((void**)&p_lin, g_lin);
    cudaGetSymbolAddress((void**)&p_es,  g_es);
    cudaGetSymbolAddress((void**)&p_ed,  g_ed);
    cudaGetSymbolAddress((void**)&p_edfp, g_edfp);
    cudaGetSymbolAddress((void**)&p_wc,  g_wc);

    const int GEMM_BLKS = (N_PANO + 63) / 64;        // 782
    const int EALL_BLKS = (E_PP + E_PF + 255) / 256; // 3321

    // ---- CSR build (shared by both pp layers) ----
    zero_cnt_kernel<<<(N_PANO + N_FP + 255) / 256, 256>>>();
    hist_kernel<<<EALL_BLKS, 256>>>(pp_dst, pf_dst);
    scan_kernel<<<2, 1024>>>();
    scatter_kernel<<<EALL_BLKS, 256>>>(pp_src, pp_dst, pf_src, pf_dst);

    compose_kernel<<<3, 256>>>(Ws0, as0, Wd0, ad0, Ws1, as1, Wd1, ad1, Wts, ats, Wtd, atd);

    // ---- layer 0 ----
    dualgemm_kernel<<<GEMM_BLKS, 256>>>(x_pano, Ws0, Lw0, p_hs, p_lin, N_PANO);
    gemv2_kernel<<<6250, 256>>>(x_pano, p_wc + 0, p_wc + 128, p_es, p_ed, N_PANO);
    agg_pp_kernel<<<6250, 256>>>(b0, Lb0);

    // ---- layer 1 ----
    dualgemm_kernel<<<GEMM_BLKS, 256>>>(p_h, Ws1, Lw1, p_hs, p_lin, N_PANO);
    gemv2_kernel<<<6250, 256>>>(p_h, p_wc + 256, p_wc + 384, p_es, p_ed, N_PANO);
    agg_pp_kernel<<<6250, 256>>>(b1, Lb1);

    // ---- translate pano -> footprint ----
    gemm64_kernel<<<GEMM_BLKS, 256>>>(p_h, Wts, p_hs, N_PANO);
    gemv1_128_kernel<<<6250, 256>>>(p_h, p_wc + 512, p_es, N_PANO);
    gemv1_64_kernel<<<1250, 256>>>(x_fp, p_wc + 640, p_edfp, N_FP);
    agg_pf_kernel<<<1250, 256>>>(bt, (float*)d_out);
}

// round 4
// speedup vs baseline: 1.2553x; 1.1520x over previous
#include <cuda_runtime.h>
#include <cuda_bf16.h>
#include <math.h>

#define N_PANO 50000
#define N_FP   10000
#define HID    128
#define OUT_D  64
#define E_PP   800000
#define E_PF   50000

// ---------------- device scratch (static, no allocation) ----------------
__device__ float g_h[N_PANO * HID];
__device__ float g_hs[N_PANO * HID];
__device__ float g_lin[N_PANO * HID];
__device__ float g_es[N_PANO];     // layer0 es
__device__ float g_ed[N_PANO];     // layer0 ed
__device__ float g_es2[N_PANO];    // layer1 es (written by agg layer0)
__device__ float g_ed2[N_PANO];    // layer1 ed
__device__ float g_es3[N_PANO];    // translate es (written by agg layer1)
__device__ float g_edfp[N_FP];
__device__ float g_wc[704];
// CSR build
__device__ int g_cnt[N_PANO];
__device__ int g_off[N_PANO + 1];
__device__ int g_cur[N_PANO];
__device__ int g_srt[E_PP];
__device__ int g_cnt_fp[N_FP];
__device__ int g_off_fp[N_FP + 1];
__device__ int g_cur_fp[N_FP];
__device__ int g_srt_fp[E_PF];

#define FMA2(d, a, b) asm("fma.rn.f32x2 %0, %1, %2, %0;" : "+l"(d) : "l"(a), "l"(b))

__device__ __forceinline__ unsigned long long dup2(float x) {
    unsigned long long r;
    asm("mov.b64 %0, {%1, %1};" : "=l"(r) : "f"(x));
    return r;
}

// ---------------- compose: w = W @ a  (tiny) ----------------
__global__ void compose_kernel(const float* __restrict__ Ws0, const float* __restrict__ as0,
                               const float* __restrict__ Wd0, const float* __restrict__ ad0,
                               const float* __restrict__ Ws1, const float* __restrict__ as1,
                               const float* __restrict__ Wd1, const float* __restrict__ ad1,
                               const float* __restrict__ Wts, const float* __restrict__ ats,
                               const float* __restrict__ Wtd, const float* __restrict__ atd) {
    int b = blockIdx.x, t = threadIdx.x;
    if (b == 0) {
        if (t < 128) {
            float s = 0.f;
            #pragma unroll 8
            for (int n = 0; n < 128; n++) s += Ws0[t * 128 + n] * as0[n];
            g_wc[t] = s;
        } else {
            int i = t - 128; float s = 0.f;
            #pragma unroll 8
            for (int n = 0; n < 128; n++) s += Wd0[i * 128 + n] * ad0[n];
            g_wc[128 + i] = s;
        }
    } else if (b == 1) {
        if (t < 128) {
            float s = 0.f;
            #pragma unroll 8
            for (int n = 0; n < 128; n++) s += Ws1[t * 128 + n] * as1[n];
            g_wc[256 + t] = s;
        } else {
            int i = t - 128; float s = 0.f;
            #pragma unroll 8
            for (int n = 0; n < 128; n++) s += Wd1[i * 128 + n] * ad1[n];
            g_wc[384 + i] = s;
        }
    } else {
        if (t < 128) {
            float s = 0.f;
            #pragma unroll 8
            for (int n = 0; n < 64; n++) s += Wts[t * 64 + n] * ats[n];
            g_wc[512 + t] = s;
        } else if (t < 192) {
            int i = t - 128; float s = 0.f;
            #pragma unroll 8
            for (int n = 0; n < 64; n++) s += Wtd[i * 64 + n] * atd[n];
            g_wc[640 + i] = s;
        }
    }
}

// ---------------- CSR build kernels ----------------
__global__ void zero_cnt_kernel() {
    int i = blockIdx.x * blockDim.x + threadIdx.x;
    if (i < N_PANO) g_cnt[i] = 0;
    else if (i < N_PANO + N_FP) g_cnt_fp[i - N_PANO] = 0;
}

__global__ void hist_kernel(const int* __restrict__ dst_pp, const int* __restrict__ dst_pf) {
    int i = blockIdx.x * blockDim.x + threadIdx.x;
    if (i < E_PP) atomicAdd(&g_cnt[dst_pp[i]], 1);
    else if (i < E_PP + E_PF) atomicAdd(&g_cnt_fp[dst_pf[i - E_PP]], 1);
}

__global__ void __launch_bounds__(1024) scan_kernel() {
    __shared__ int totals[1024];
    const int N = (blockIdx.x == 0) ? N_PANO : N_FP;
    int* cnt = (blockIdx.x == 0) ? g_cnt : g_cnt_fp;
    int* off = (blockIdx.x == 0) ? g_off : g_off_fp;
    int* cur = (blockIdx.x == 0) ? g_cur : g_cur_fp;
    int t = threadIdx.x;
    int C = (N + 1023) / 1024;
    int lo = t * C;
    int hi = lo + C; if (hi > N) hi = N; if (lo > N) lo = N;
    int sum = 0;
    for (int i = lo; i < hi; i++) sum += cnt[i];
    totals[t] = sum;
    __syncthreads();
    #pragma unroll
    for (int o = 1; o < 1024; o <<= 1) {
        int v = (t >= o) ? totals[t - o] : 0;
        __syncthreads();
        totals[t] += v;
        __syncthreads();
    }
    int run = (t == 0) ? 0 : totals[t - 1];
    for (int i = lo; i < hi; i++) {
        off[i] = run; cur[i] = run;
        run += cnt[i];
    }
    if (hi == N) off[N] = run;
}

__global__ void scatter_kernel(const int* __restrict__ src_pp, const int* __restrict__ dst_pp,
                               const int* __restrict__ src_pf, const int* __restrict__ dst_pf) {
    int i = blockIdx.x * blockDim.x + threadIdx.x;
    if (i < E_PP) {
        int pos = atomicAdd(&g_cur[dst_pp[i]], 1);
        g_srt[pos] = src_pp[i];
    } else if (i < E_PP + E_PF) {
        int j = i - E_PP;
        int pos = atomicAdd(&g_cur_fp[dst_pf[j]], 1);
        g_srt_fp[pos] = src_pf[j];
    }
}

// ---------------- fused dual GEMM: C1 = A@B1, C2 = A@B2 ([M,128]x[128,128]) ----------------
// A transposed+swizzled in SMEM (warp-broadcast reads); f32x2 packed along M.
// Per-thread: 8 rows x 4 cols x 2 matrices.
__global__ void __launch_bounds__(256) dualgemm_kernel(const float* __restrict__ A,
                                                       const float* __restrict__ B1,
                                                       const float* __restrict__ B2,
                                                       float* __restrict__ C1,
                                                       float* __restrict__ C2, int M) {
    __shared__ float At[32 * 64];    // [k][swizzled row] 8 KB
    __shared__ float Bs1[32 * 128];  // 16 KB
    __shared__ float Bs2[32 * 128];  // 16 KB
    const int tid = threadIdx.x;
    const int m0 = blockIdx.x * 64;
    const int tx = tid & 31;         // col group (4 cols)
    const int ty = tid >> 5;         // row group (8 rows)
    const int g0 = 2 * ty, g1 = 2 * ty + 1;

    unsigned long long acc1[4][4], acc2[4][4];
    #pragma unroll
    for (int p = 0; p < 4; p++)
        #pragma unroll
        for (int c = 0; c < 4; c++) { acc1[p][c] = 0ull; acc2[p][c] = 0ull; }

    #pragma unroll 1
    for (int k0 = 0; k0 < 128; k0 += 32) {
        // A tile: 64 rows x 32 k -> transposed store with XOR swizzle
        #pragma unroll
        for (int l = 0; l < 2; l++) {
            int idx = tid + l * 256;             // 0..511 float4s
            int r = idx >> 3;                    // 0..63
            int c = (idx & 7) * 4;               // k within tile
            float4 v = make_float4(0.f, 0.f, 0.f, 0.f);
            if (m0 + r < M) v = *(const float4*)&A[(size_t)(m0 + r) * 128 + k0 + c];
            int sg = ((r >> 2) ^ (idx & 7)) * 4 + (r & 3);   // swizzled slot
            At[(c + 0) * 64 + sg] = v.x;
            At[(c + 1) * 64 + sg] = v.y;
            At[(c + 2) * 64 + sg] = v.z;
            At[(c + 3) * 64 + sg] = v.w;
        }
        // B tiles (contiguous)
        const float4* b1g = (const float4*)(B1 + k0 * 128);
        const float4* b2g = (const float4*)(B2 + k0 * 128);
        #pragma unroll
        for (int l = 0; l < 4; l++) {
            int idx = tid + l * 256;
            ((float4*)Bs1)[idx] = b1g[idx];
            ((float4*)Bs2)[idx] = b2g[idx];
        }
        __syncthreads();
        #pragma unroll 4
        for (int k = 0; k < 32; k++) {
            int sw = k >> 2;
            ulonglong2 u0 = *(const ulonglong2*)&At[k * 64 + ((g0 ^ sw) << 2)];
            ulonglong2 u1 = *(const ulonglong2*)&At[k * 64 + ((g1 ^ sw) << 2)];
            float4 b1 = *(const float4*)&Bs1[k * 128 + tx * 4];
            float4 b2 = *(const float4*)&Bs2[k * 128 + tx * 4];
            unsigned long long bd1[4] = {dup2(b1.x), dup2(b1.y), dup2(b1.z), dup2(b1.w)};
            unsigned long long bd2[4] = {dup2(b2.x), dup2(b2.y), dup2(b2.z), dup2(b2.w)};
            unsigned long long ap[4] = {u0.x, u0.y, u1.x, u1.y};
            #pragma unroll
            for (int p = 0; p < 4; p++) {
                FMA2(acc1[p][0], ap[p], bd1[0]);
                FMA2(acc1[p][1], ap[p], bd1[1]);
                FMA2(acc1[p][2], ap[p], bd1[2]);
                FMA2(acc1[p][3], ap[p], bd1[3]);
                FMA2(acc2[p][0], ap[p], bd2[0]);
                FMA2(acc2[p][1], ap[p], bd2[1]);
                FMA2(acc2[p][2], ap[p], bd2[2]);
                FMA2(acc2[p][3], ap[p], bd2[3]);
            }
        }
        __syncthreads();
    }
    #pragma unroll
    for (int p = 0; p < 4; p++) {
        int r = m0 + ty * 8 + p * 2;
        float2 c10 = *(float2*)&acc1[p][0], c11 = *(float2*)&acc1[p][1];
        float2 c12 = *(float2*)&acc1[p][2], c13 = *(float2*)&acc1[p][3];
        float2 c20 = *(float2*)&acc2[p][0], c21 = *(float2*)&acc2[p][1];
        float2 c22 = *(float2*)&acc2[p][2], c23 = *(float2*)&acc2[p][3];
        if (r < M) {
            *(float4*)&C1[(size_t)r * 128 + tx * 4] = make_float4(c10.x, c11.x, c12.x, c13.x);
            *(float4*)&C2[(size_t)r * 128 + tx * 4] = make_float4(c20.x, c21.x, c22.x, c23.x);
        }
        if (r + 1 < M) {
            *(float4*)&C1[(size_t)(r + 1) * 128 + tx * 4] = make_float4(c10.y, c11.y, c12.y, c13.y);
            *(float4*)&C2[(size_t)(r + 1) * 128 + tx * 4] = make_float4(c20.y, c21.y, c22.y, c23.y);
        }
    }
}

// ---------------- GEMM: C[M,64] = A[M,128] @ B[128,64] (same scheme) ----------------
__global__ void __launch_bounds__(256) gemm64_kernel(const float* __restrict__ A,
                                                     const float* __restrict__ B,
                                                     float* __restrict__ C, int M) {
    __shared__ float At[32 * 64];   // 8 KB
    __shared__ float Bs[32 * 64];   // 8 KB
    const int tid = threadIdx.x;
    const int m0 = blockIdx.x * 64;
    const int tx = tid & 31;        // col group (2 cols)
    const int ty = tid >> 5;        // row group (8 rows)
    const int g0 = 2 * ty, g1 = 2 * ty + 1;

    unsigned long long acc[4][2];
    #pragma unroll
    for (int p = 0; p < 4; p++) { acc[p][0] = 0ull; acc[p][1] = 0ull; }

    #pragma unroll 1
    for (int k0 = 0; k0 < 128; k0 += 32) {
        #pragma unroll
        for (int l = 0; l < 2; l++) {
            int idx = tid + l * 256;
            int r = idx >> 3;
            int c = (idx & 7) * 4;
            float4 v = make_float4(0.f, 0.f, 0.f, 0.f);
            if (m0 + r < M) v = *(const float4*)&A[(size_t)(m0 + r) * 128 + k0 + c];
            int sg = ((r >> 2) ^ (idx & 7)) * 4 + (r & 3);
            At[(c + 0) * 64 + sg] = v.x;
            At[(c + 1) * 64 + sg] = v.y;
            At[(c + 2) * 64 + sg] = v.z;
            At[(c + 3) * 64 + sg] = v.w;
        }
        const float4* bg = (const float4*)(B + k0 * 64);
        #pragma unroll
        for (int l = 0; l < 2; l++) {
            int idx = tid + l * 256;
            ((float4*)Bs)[idx] = bg[idx];
        }
        __syncthreads();
        #pragma unroll 4
        for (int k = 0; k < 32; k++) {
            int sw = k >> 2;
            ulonglong2 u0 = *(const ulonglong2*)&At[k * 64 + ((g0 ^ sw) << 2)];
            ulonglong2 u1 = *(const ulonglong2*)&At[k * 64 + ((g1 ^ sw) << 2)];
            float2 b = *(const float2*)&Bs[k * 64 + tx * 2];
            unsigned long long bd0 = dup2(b.x), bd1 = dup2(b.y);
            unsigned long long ap[4] = {u0.x, u0.y, u1.x, u1.y};
            #pragma unroll
            for (int p = 0; p < 4; p++) {
                FMA2(acc[p][0], ap[p], bd0);
                FMA2(acc[p][1], ap[p], bd1);
            }
        }
        __syncthreads();
    }
    #pragma unroll
    for (int p = 0; p < 4; p++) {
        int r = m0 + ty * 8 + p * 2;
        float2 c0 = *(float2*)&acc[p][0], c1 = *(float2*)&acc[p][1];
        if (r < M)     *(float2*)&C[(size_t)r * 64 + tx * 2]       = make_float2(c0.x, c1.x);
        if (r + 1 < M) *(float2*)&C[(size_t)(r + 1) * 64 + tx * 2] = make_float2(c0.y, c1.y);
    }
}

// ---------------- GEMVs ----------------
__global__ void gemv2_kernel(const float* __restrict__ X, const float* __restrict__ wa,
                             const float* __restrict__ wb,
                             float* __restrict__ ea, float* __restrict__ eb, int M) {
    int gw = (blockIdx.x * blockDim.x + threadIdx.x) >> 5;
    int lane = threadIdx.x & 31;
    if (gw >= M) return;
    float4 x = *(const float4*)&X[(size_t)gw * 128 + lane * 4];
    float4 a = *(const float4*)&wa[lane * 4];
    float4 b = *(const float4*)&wb[lane * 4];
    float sa = x.x * a.x + x.y * a.y + x.z * a.z + x.w * a.w;
    float sb = x.x * b.x + x.y * b.y + x.z * b.z + x.w * b.w;
    #pragma unroll
    for (int o = 16; o; o >>= 1) {
        sa += __shfl_xor_sync(0xFFFFFFFFu, sa, o);
        sb += __shfl_xor_sync(0xFFFFFFFFu, sb, o);
    }
    if (lane == 0) { ea[gw] = sa; eb[gw] = sb; }
}

__global__ void gemv1_64_kernel(const float* __restrict__ X, const float* __restrict__ w,
                                float* __restrict__ out, int M) {
    int gw = (blockIdx.x * blockDim.x + threadIdx.x) >> 5;
    int lane = threadIdx.x & 31;
    if (gw >= M) return;
    float2 x = *(const float2*)&X[(size_t)gw * 64 + lane * 2];
    float2 a = *(const float2*)&w[lane * 2];
    float s = x.x * a.x + x.y * a.y;
    #pragma unroll
    for (int o = 16; o; o >>= 1) s += __shfl_xor_sync(0xFFFFFFFFu, s, o);
    if (lane == 0) out[gw] = s;
}

// ---------------- CSR aggregation + fused finalize (pano layer) ----------------
// One warp per dst node. Also computes next-stage attention dots from the
// freshly produced h row (wa/wb composed vectors), written to ea/eb.
__global__ void __launch_bounds__(256) agg_pp_kernel(const float* __restrict__ b,
                                                     const float* __restrict__ Lb,
                                                     const float* __restrict__ es_in,
                                                     const float* __restrict__ ed_in,
                                                     const float* __restrict__ wa,
                                                     const float* __restrict__ wb,
                                                     float* __restrict__ ea,
                                                     float* __restrict__ eb) {
    int gw = (blockIdx.x * blockDim.x + threadIdx.x) >> 5;
    int lane = threadIdx.x & 31;
    if (gw >= N_PANO) return;
    int start = g_off[gw];
    int end   = g_off[gw + 1];
    float edd = ed_in[gw];
    float4 acc = make_float4(0.f, 0.f, 0.f, 0.f);
    float exsum = 0.f;
    for (int base = start; base < end; base += 32) {
        int m = end - base; if (m > 32) m = 32;
        int s = 0; float ex = 0.f;
        if (lane < m) {
            s = g_srt[base + lane];
            float ez = es_in[s] + edd;
            float e = ez > 0.f ? ez : 0.2f * ez;
            ex = __expf(e);
        }
        exsum += ex;
        for (int j = 0; j < m; j++) {
            int sj   = __shfl_sync(0xFFFFFFFFu, s, j);
            float xj = __shfl_sync(0xFFFFFFFFu, ex, j);
            float4 h = *(const float4*)&g_hs[(size_t)sj * 128 + lane * 4];
            acc.x += h.x * xj; acc.y += h.y * xj;
            acc.z += h.z * xj; acc.w += h.w * xj;
        }
    }
    #pragma unroll
    for (int o = 16; o; o >>= 1) exsum += __shfl_xor_sync(0xFFFFFFFFu, exsum, o);
    float inv = exsum > 0.f ? 1.f / exsum : 0.f;
    float4 l  = *(const float4*)&g_lin[(size_t)gw * 128 + lane * 4];
    float4 bb = *(const float4*)&b[lane * 4];
    float4 lb = *(const float4*)&Lb[lane * 4];
    float4 r;
    r.x = fmaxf(acc.x * inv + bb.x + l.x + lb.x, 0.f);
    r.y = fmaxf(acc.y * inv + bb.y + l.y + lb.y, 0.f);
    r.z = fmaxf(acc.z * inv + bb.z + l.z + lb.z, 0.f);
    r.w = fmaxf(acc.w * inv + bb.w + l.w + lb.w, 0.f);
    *(float4*)&g_h[(size_t)gw * 128 + lane * 4] = r;
    // fused attention dots for the next stage
    float4 a4 = *(const float4*)&wa[lane * 4];
    float sa = r.x * a4.x + r.y * a4.y + r.z * a4.z + r.w * a4.w;
    float sb = 0.f;
    if (eb) {
        float4 b4 = *(const float4*)&wb[lane * 4];
        sb = r.x * b4.x + r.y * b4.y + r.z * b4.z + r.w * b4.w;
    }
    #pragma unroll
    for (int o = 16; o; o >>= 1) {
        sa += __shfl_xor_sync(0xFFFFFFFFu, sa, o);
        sb += __shfl_xor_sync(0xFFFFFFFFu, sb, o);
    }
    if (lane == 0) {
        ea[gw] = sa;
        if (eb) eb[gw] = sb;
    }
}

// ---------------- CSR aggregation (translate) -> d_out ----------------
__global__ void __launch_bounds__(256) agg_pf_kernel(const float* __restrict__ bt,
                                                     float* __restrict__ out) {
    int gw = (blockIdx.x * blockDim.x + threadIdx.x) >> 5;
    int lane = threadIdx.x & 31;
    if (gw >= N_FP) return;
    int start = g_off_fp[gw];
    int end   = g_off_fp[gw + 1];
    float edd = g_edfp[gw];
    float2 acc = make_float2(0.f, 0.f);
    float exsum = 0.f;
    for (int base = start; base < end; base += 32) {
        int m = end - base; if (m > 32) m = 32;
        int s = 0; float ex = 0.f;
        if (lane < m) {
            s = g_srt_fp[base + lane];
            float ez = g_es3[s] + edd;
            float e = ez > 0.f ? ez : 0.2f * ez;
            ex = __expf(e);
        }
        exsum += ex;
        for (int j = 0; j < m; j++) {
            int sj   = __shfl_sync(0xFFFFFFFFu, s, j);
            float xj = __shfl_sync(0xFFFFFFFFu, ex, j);
            float2 h = *(const float2*)&g_hs[(size_t)sj * 64 + lane * 2];
            acc.x += h.x * xj; acc.y += h.y * xj;
        }
    }
    #pragma unroll
    for (int o = 16; o; o >>= 1) exsum += __shfl_xor_sync(0xFFFFFFFFu, exsum, o);
    float inv = exsum > 0.f ? 1.f / exsum : 0.f;
    float2 bb = *(const float2*)&bt[lane * 2];
    float2 r;
    r.x = acc.x * inv + bb.x;
    r.y = acc.y * inv + bb.y;
    *(float2*)&out[(size_t)gw * 64 + lane * 2] = r;
}

// ---------------- launch ----------------
extern "C" void kernel_launch(void* const* d_in, const int* in_sizes, int n_in,
                              void* d_out, int out_size) {
    const float* x_pano = (const float*)d_in[0];
    const float* x_fp   = (const float*)d_in[1];
    const float* Ws0 = (const float*)d_in[2];
    const float* Wd0 = (const float*)d_in[3];
    const float* as0 = (const float*)d_in[4];
    const float* ad0 = (const float*)d_in[5];
    const float* b0  = (const float*)d_in[6];
    const float* Lw0 = (const float*)d_in[7];
    const float* Lb0 = (const float*)d_in[8];
    const float* Ws1 = (const float*)d_in[9];
    const float* Wd1 = (const float*)d_in[10];
    const float* as1 = (const float*)d_in[11];
    const float* ad1 = (const float*)d_in[12];
    const float* b1  = (const float*)d_in[13];
    const float* Lw1 = (const float*)d_in[14];
    const float* Lb1 = (const float*)d_in[15];
    const float* Wts = (const float*)d_in[16];
    const float* Wtd = (const float*)d_in[17];
    const float* ats = (const float*)d_in[18];
    const float* atd = (const float*)d_in[19];
    const float* bt  = (const float*)d_in[20];
    const int* edge_pp = (const int*)d_in[21];
    const int* pf_src  = (const int*)d_in[22];
    const int* pf_dst  = (const int*)d_in[23];
    const int* pp_src = edge_pp;
    const int* pp_dst = edge_pp + E_PP;

    float *p_h, *p_hs, *p_lin, *p_es, *p_ed, *p_es2, *p_ed2, *p_es3, *p_edfp, *p_wc;
    cudaGetSymbolAddress((void**)&p_h,    g_h);
    cudaGetSymbolAddress((void**)&p_hs,   g_hs);
    cudaGetSymbolAddress((void**)&p_lin,  g_lin);
    cudaGetSymbolAddress((void**)&p_es,   g_es);
    cudaGetSymbolAddress((void**)&p_ed,   g_ed);
    cudaGetSymbolAddress((void**)&p_es2,  g_es2);
    cudaGetSymbolAddress((void**)&p_ed2,  g_ed2);
    cudaGetSymbolAddress((void**)&p_es3,  g_es3);
    cudaGetSymbolAddress((void**)&p_edfp, g_edfp);
    cudaGetSymbolAddress((void**)&p_wc,   g_wc);

    const int GEMM_BLKS = (N_PANO + 63) / 64;        // 782
    const int EALL_BLKS = (E_PP + E_PF + 255) / 256; // 3321

    // ---- CSR build (shared by both pp layers) ----
    zero_cnt_kernel<<<(N_PANO + N_FP + 255) / 256, 256>>>();
    hist_kernel<<<EALL_BLKS, 256>>>(pp_dst, pf_dst);
    scan_kernel<<<2, 1024>>>();
    scatter_kernel<<<EALL_BLKS, 256>>>(pp_src, pp_dst, pf_src, pf_dst);

    compose_kernel<<<3, 256>>>(Ws0, as0, Wd0, ad0, Ws1, as1, Wd1, ad1, Wts, ats, Wtd, atd);

    // ---- layer 0 ----
    dualgemm_kernel<<<GEMM_BLKS, 256>>>(x_pano, Ws0, Lw0, p_hs, p_lin, N_PANO);
    gemv2_kernel<<<6250, 256>>>(x_pano, p_wc + 0, p_wc + 128, p_es, p_ed, N_PANO);
    // agg writes h, and computes layer-1 es/ed from h
    agg_pp_kernel<<<6250, 256>>>(b0, Lb0, p_es, p_ed, p_wc + 256, p_wc + 384, p_es2, p_ed2);

    // ---- layer 1 ----
    dualgemm_kernel<<<GEMM_BLKS, 256>>>(p_h, Ws1, Lw1, p_hs, p_lin, N_PANO);
    // agg writes h2, and computes translate es from h2
    agg_pp_kernel<<<6250, 256>>>(b1, Lb1, p_es2, p_ed2, p_wc + 512, (const float*)0, p_es3, (float*)0);

    // ---- translate pano -> footprint ----
    gemm64_kernel<<<GEMM_BLKS, 256>>>(p_h, Wts, p_hs, N_PANO);
    gemv1_64_kernel<<<1250, 256>>>(x_fp, p_wc + 640, p_edfp, N_FP);
    agg_pf_kernel<<<1250, 256>>>(bt, (float*)d_out);
}

// round 6
// speedup vs baseline: 1.5175x; 1.2088x over previous
#include <cuda_runtime.h>
#include <cuda_bf16.h>
#include <math.h>
#include <stdint.h>
#include <string.h>

#define N_PANO 50000
#define N_FP   10000
#define HID    128
#define E_PP   800000
#define E_PF   50000

typedef unsigned short ushort_t;

// ---------------- device scratch (static, no allocation) ----------------
__device__ float g_hs[N_PANO * HID];
__device__ float g_lin[N_PANO * HID];
__device__ float g_es[N_PANO];
__device__ float g_ed[N_PANO];
__device__ float g_es2[N_PANO];
__device__ float g_ed2[N_PANO];
__device__ float g_es3[N_PANO];
__device__ float g_edfp[N_FP];
__device__ float g_wc[704];
// split-bf16 activation images (reused layer0 -> layer1 -> translate)
__device__ ushort_t g_ahi[N_PANO * 128];
__device__ ushort_t g_alo[N_PANO * 128];
// split-bf16 weight images, [N][K] row-major (B col-major for mma.row.col)
__device__ ushort_t g_wb0hi[256 * 128], g_wb0lo[256 * 128];
__device__ ushort_t g_wb1hi[256 * 128], g_wb1lo[256 * 128];
__device__ ushort_t g_wbthi[64 * 128],  g_wbtlo[64 * 128];
// CSR build
__device__ int g_cnt[N_PANO];
__device__ int g_off[N_PANO + 1];
__device__ int g_cur[N_PANO];
__device__ int g_srt[E_PP];
__device__ int g_cnt_fp[N_FP];
__device__ int g_off_fp[N_FP + 1];
__device__ int g_cur_fp[N_FP];
__device__ int g_srt_fp[E_PF];

// ---------------- helpers ----------------
__device__ __forceinline__ uint32_t smem_u32(const void* p) {
    uint32_t a;
    asm("{ .reg .u64 t; cvta.to.shared.u64 t, %1; cvt.u32.u64 %0, t; }" : "=r"(a) : "l"(p));
    return a;
}
__device__ __forceinline__ void ldsm_x4(uint32_t* r, uint32_t addr) {
    asm volatile("ldmatrix.sync.aligned.m8n8.x4.shared.b16 {%0,%1,%2,%3}, [%4];"
                 : "=r"(r[0]), "=r"(r[1]), "=r"(r[2]), "=r"(r[3]) : "r"(addr));
}
__device__ __forceinline__ void ldsm_x2(uint32_t* r, uint32_t addr) {
    asm volatile("ldmatrix.sync.aligned.m8n8.x2.shared.b16 {%0,%1}, [%2];"
                 : "=r"(r[0]), "=r"(r[1]) : "r"(addr));
}
__device__ __forceinline__ void mma16816(float* d, const uint32_t* a, const uint32_t* b) {
    asm volatile("mma.sync.aligned.m16n8k16.row.col.f32.bf16.bf16.f32 "
                 "{%0,%1,%2,%3}, {%4,%5,%6,%7}, {%8,%9}, {%0,%1,%2,%3};"
                 : "+f"(d[0]), "+f"(d[1]), "+f"(d[2]), "+f"(d[3])
                 : "r"(a[0]), "r"(a[1]), "r"(a[2]), "r"(a[3]), "r"(b[0]), "r"(b[1]));
}
__device__ __forceinline__ void split_bf16(float v, ushort_t& h, ushort_t& l) {
    __nv_bfloat16 hb = __float2bfloat16(v);
    float r = v - __bfloat162float(hb);
    __nv_bfloat16 lb = __float2bfloat16(r);
    memcpy(&h, &hb, 2); memcpy(&l, &lb, 2);
}

// ---------------- weight prep: split to bf16 hi/lo, [N][K] row-major ----------------
__global__ void prep_b_kernel(const float* __restrict__ Ws0, const float* __restrict__ Lw0,
                              const float* __restrict__ Ws1, const float* __restrict__ Lw1,
                              const float* __restrict__ Wts) {
    int idx = blockIdx.x * blockDim.x + threadIdx.x;   // 73728 total
    ushort_t *ih, *il;
    int n, k;
    float v;
    if (idx < 32768) {
        n = idx >> 7; k = idx & 127;
        v = (n < 128) ? Ws0[k * 128 + n] : Lw0[k * 128 + (n - 128)];
        ih = g_wb0hi; il = g_wb0lo;
    } else if (idx < 65536) {
        int e = idx - 32768;
        n = e >> 7; k = e & 127;
        v = (n < 128) ? Ws1[k * 128 + n] : Lw1[k * 128 + (n - 128)];
        ih = g_wb1hi; il = g_wb1lo;
    } else if (idx < 73728) {
        int e = idx - 65536;
        n = e >> 7; k = e & 127;
        v = Wts[k * 64 + n];
        ih = g_wbthi; il = g_wbtlo;
    } else return;
    ushort_t h, l;
    split_bf16(v, h, l);
    ih[n * 128 + k] = h;
    il[n * 128 + k] = l;
}

// ---------------- HMMA GEMM: C[M,NTOT] = A[M,128] @ W, split-bf16 3 terms ----------------
// NT = CTA n-tile (128 or 64). grid.y covers NTOT/128 halves (C1 then C2).
template<int NT>
__global__ void __launch_bounds__(256) mmagemm_kernel(
        const ushort_t* __restrict__ Ahi, const ushort_t* __restrict__ Alo,
        const ushort_t* __restrict__ Bhi, const ushort_t* __restrict__ Blo,
        float* __restrict__ C1, float* __restrict__ C2, int M) {
    constexpr int NTW = NT / 4;       // warp n width (32 or 16)
    constexpr int NTILES = NTW / 8;   // n-tiles per warp (4 or 2)
    __shared__ ushort_t As[2][128][40];
    __shared__ ushort_t Bs[2][NT][40];
    const int tid = threadIdx.x;
    const int wid = tid >> 5, lane = tid & 31;
    const int wm = wid >> 2, wn = wid & 3;
    const int m0 = blockIdx.x * 128;
    const int nb = blockIdx.y * 128;

    float d[4][NTILES][4];
    #pragma unroll
    for (int mt = 0; mt < 4; mt++)
        #pragma unroll
        for (int nt = 0; nt < NTILES; nt++)
            #pragma unroll
            for (int j = 0; j < 4; j++) d[mt][nt][j] = 0.f;

    #pragma unroll 1
    for (int k0 = 0; k0 < 128; k0 += 32) {
        // A tiles (hi, lo): 128 rows x 32 bf16 = 512 x 16B per image
        #pragma unroll
        for (int l = 0; l < 2; l++) {
            int i = tid + l * 256;
            int r = i >> 2, s = i & 3;
            uint4 vh = make_uint4(0, 0, 0, 0), vl = make_uint4(0, 0, 0, 0);
            if (m0 + r < M) {
                vh = *(const uint4*)&Ahi[(size_t)(m0 + r) * 128 + k0 + s * 8];
                vl = *(const uint4*)&Alo[(size_t)(m0 + r) * 128 + k0 + s * 8];
            }
            *(uint4*)&As[0][r][s * 8] = vh;
            *(uint4*)&As[1][r][s * 8] = vl;
        }
        // B tiles: NT rows x 32 bf16
        #pragma unroll
        for (int l = 0; l < (NT * 4) / 256; l++) {
            int i = tid + l * 256;
            int r = i >> 2, s = i & 3;
            *(uint4*)&Bs[0][r][s * 8] = *(const uint4*)&Bhi[(size_t)(nb + r) * 128 + k0 + s * 8];
            *(uint4*)&Bs[1][r][s * 8] = *(const uint4*)&Blo[(size_t)(nb + r) * 128 + k0 + s * 8];
        }
        __syncthreads();
        #pragma unroll
        for (int kk = 0; kk < 32; kk += 16) {
            uint32_t ah[4][4], al[4][4], bh[NTILES][2], bl[NTILES][2];
            #pragma unroll
            for (int mt = 0; mt < 4; mt++) {
                int ar = wm * 64 + mt * 16 + (lane & 15);
                int ac = kk + (lane >> 4) * 8;
                ldsm_x4(ah[mt], smem_u32(&As[0][ar][ac]));
                ldsm_x4(al[mt], smem_u32(&As[1][ar][ac]));
            }
            #pragma unroll
            for (int nt = 0; nt < NTILES; nt++) {
                int l16 = lane & 15;
                int br = wn * NTW + nt * 8 + (l16 & 7);
                int bc = kk + (l16 >> 3) * 8;
                ldsm_x2(bh[nt], smem_u32(&Bs[0][br][bc]));
                ldsm_x2(bl[nt], smem_u32(&Bs[1][br][bc]));
            }
            #pragma unroll
            for (int mt = 0; mt < 4; mt++)
                #pragma unroll
                for (int nt = 0; nt < NTILES; nt++) {
                    mma16816(d[mt][nt], ah[mt], bh[nt]);
                    mma16816(d[mt][nt], al[mt], bh[nt]);
                    mma16816(d[mt][nt], ah[mt], bl[nt]);
                }
        }
        __syncthreads();
    }
    float* C = (NT == 64 || blockIdx.y == 0) ? C1 : C2;
    const int cstride = (NT == 64) ? 64 : 128;
    #pragma unroll
    for (int mt = 0; mt < 4; mt++) {
        int r0 = m0 + wm * 64 + mt * 16 + (lane >> 2);
        #pragma unroll
        for (int nt = 0; nt < NTILES; nt++) {
            int c = wn * NTW + nt * 8 + (lane & 3) * 2;
            if (r0 < M)
                *(float2*)&C[(size_t)r0 * cstride + c] = make_float2(d[mt][nt][0], d[mt][nt][1]);
            if (r0 + 8 < M)
                *(float2*)&C[(size_t)(r0 + 8) * cstride + c] = make_float2(d[mt][nt][2], d[mt][nt][3]);
        }
    }
}

// ---------------- compose: w = W @ a  (tiny) ----------------
__global__ void compose_kernel(const float* __restrict__ Ws0, const float* __restrict__ as0,
                               const float* __restrict__ Wd0, const float* __restrict__ ad0,
                               const float* __restrict__ Ws1, const float* __restrict__ as1,
                               const float* __restrict__ Wd1, const float* __restrict__ ad1,
                               const float* __restrict__ Wts, const float* __restrict__ ats,
                               const float* __restrict__ Wtd, const float* __restrict__ atd) {
    int b = blockIdx.x, t = threadIdx.x;
    if (b == 0) {
        if (t < 128) {
            float s = 0.f;
            for (int n = 0; n < 128; n++) s += Ws0[t * 128 + n] * as0[n];
            g_wc[t] = s;
        } else {
            int i = t - 128; float s = 0.f;
            for (int n = 0; n < 128; n++) s += Wd0[i * 128 + n] * ad0[n];
            g_wc[128 + i] = s;
        }
    } else if (b == 1) {
        if (t < 128) {
            float s = 0.f;
            for (int n = 0; n < 128; n++) s += Ws1[t * 128 + n] * as1[n];
            g_wc[256 + t] = s;
        } else {
            int i = t - 128; float s = 0.f;
            for (int n = 0; n < 128; n++) s += Wd1[i * 128 + n] * ad1[n];
            g_wc[384 + i] = s;
        }
    } else {
        if (t < 128) {
            float s = 0.f;
            for (int n = 0; n < 64; n++) s += Wts[t * 64 + n] * ats[n];
            g_wc[512 + t] = s;
        } else if (t < 192) {
            int i = t - 128; float s = 0.f;
            for (int n = 0; n < 64; n++) s += Wtd[i * 64 + n] * atd[n];
            g_wc[640 + i] = s;
        }
    }
}

// ---------------- CSR build kernels ----------------
__global__ void zero_cnt_kernel() {
    int i = blockIdx.x * blockDim.x + threadIdx.x;
    if (i < N_PANO) g_cnt[i] = 0;
    else if (i < N_PANO + N_FP) g_cnt_fp[i - N_PANO] = 0;
}

__global__ void hist_kernel(const int* __restrict__ dst_pp, const int* __restrict__ dst_pf) {
    int i = blockIdx.x * blockDim.x + threadIdx.x;
    if (i < E_PP) atomicAdd(&g_cnt[dst_pp[i]], 1);
    else if (i < E_PP + E_PF) atomicAdd(&g_cnt_fp[dst_pf[i - E_PP]], 1);
}

__global__ void __launch_bounds__(1024) scan_kernel() {
    __shared__ int totals[1024];
    const int N = (blockIdx.x == 0) ? N_PANO : N_FP;
    int* cnt = (blockIdx.x == 0) ? g_cnt : g_cnt_fp;
    int* off = (blockIdx.x == 0) ? g_off : g_off_fp;
    int* cur = (blockIdx.x == 0) ? g_cur : g_cur_fp;
    int t = threadIdx.x;
    int C = (N + 1023) / 1024;
    int lo = t * C;
    int hi = lo + C; if (hi > N) hi = N; if (lo > N) lo = N;
    int sum = 0;
    for (int i = lo; i < hi; i++) sum += cnt[i];
    totals[t] = sum;
    __syncthreads();
    #pragma unroll
    for (int o = 1; o < 1024; o <<= 1) {
        int v = (t >= o) ? totals[t - o] : 0;
        __syncthreads();
        totals[t] += v;
        __syncthreads();
    }
    int run = (t == 0) ? 0 : totals[t - 1];
    for (int i = lo; i < hi; i++) {
        off[i] = run; cur[i] = run;
        run += cnt[i];
    }
    if (hi == N) off[N] = run;
}

__global__ void scatter_kernel(const int* __restrict__ src_pp, const int* __restrict__ dst_pp,
                               const int* __restrict__ src_pf, const int* __restrict__ dst_pf) {
    int i = blockIdx.x * blockDim.x + threadIdx.x;
    if (i < E_PP) {
        int pos = atomicAdd(&g_cur[dst_pp[i]], 1);
        g_srt[pos] = src_pp[i];
    } else if (i < E_PP + E_PF) {
        int j = i - E_PP;
        int pos = atomicAdd(&g_cur_fp[dst_pf[j]], 1);
        g_srt_fp[pos] = src_pf[j];
    }
}

// ---------------- GEMV (layer 0) + fused bf16 split of x_pano ----------------
__global__ void gemv2s_kernel(const float* __restrict__ X, const float* __restrict__ wa,
                              const float* __restrict__ wb,
                              float* __restrict__ ea, float* __restrict__ eb, int M) {
    int gw = (blockIdx.x * blockDim.x + threadIdx.x) >> 5;
    int lane = threadIdx.x & 31;
    if (gw >= M) return;
    float4 x = *(const float4*)&X[(size_t)gw * 128 + lane * 4];
    // split to bf16 hi/lo images for the tensor GEMM
    ushort4 h4, l4;
    split_bf16(x.x, h4.x, l4.x); split_bf16(x.y, h4.y, l4.y);
    split_bf16(x.z, h4.z, l4.z); split_bf16(x.w, h4.w, l4.w);
    *(ushort4*)&g_ahi[(size_t)gw * 128 + lane * 4] = h4;
    *(ushort4*)&g_alo[(size_t)gw * 128 + lane * 4] = l4;
    float4 a = *(const float4*)&wa[lane * 4];
    float4 b = *(const float4*)&wb[lane * 4];
    float sa = x.x * a.x + x.y * a.y + x.z * a.z + x.w * a.w;
    float sb = x.x * b.x + x.y * b.y + x.z * b.z + x.w * b.w;
    #pragma unroll
    for (int o = 16; o; o >>= 1) {
        sa += __shfl_xor_sync(0xFFFFFFFFu, sa, o);
        sb += __shfl_xor_sync(0xFFFFFFFFu, sb, o);
    }
    if (lane == 0) { ea[gw] = sa; eb[gw] = sb; }
}

__global__ void gemv1_64_kernel(const float* __restrict__ X, const float* __restrict__ w,
                                float* __restrict__ out, int M) {
    int gw = (blockIdx.x * blockDim.x + threadIdx.x) >> 5;
    int lane = threadIdx.x & 31;
    if (gw >= M) return;
    float2 x = *(const float2*)&X[(size_t)gw * 64 + lane * 2];
    float2 a = *(const float2*)&w[lane * 2];
    float s = x.x * a.x + x.y * a.y;
    #pragma unroll
    for (int o = 16; o; o >>= 1) s += __shfl_xor_sync(0xFFFFFFFFu, s, o);
    if (lane == 0) out[gw] = s;
}

// ---------------- CSR aggregation + fused finalize + next-stage dots + bf16 split ----------------
__global__ void __launch_bounds__(256) agg_pp_kernel(const float* __restrict__ b,
                                                     const float* __restrict__ Lb,
                                                     const float* __restrict__ es_in,
                                                     const float* __restrict__ ed_in,
                                                     const float* __restrict__ wa,
                                                     const float* __restrict__ wb,
                                                     float* __restrict__ ea,
                                                     float* __restrict__ eb) {
    int gw = (blockIdx.x * blockDim.x + threadIdx.x) >> 5;
    int lane = threadIdx.x & 31;
    if (gw >= N_PANO) return;
    int start = g_off[gw];
    int end   = g_off[gw + 1];
    float edd = ed_in[gw];
    float4 acc = make_float4(0.f, 0.f, 0.f, 0.f);
    float exsum = 0.f;
    for (int base = start; base < end; base += 32) {
        int m = end - base; if (m > 32) m = 32;
        int s = 0; float ex = 0.f;
        if (lane < m) {
            s = g_srt[base + lane];
            float ez = es_in[s] + edd;
            float e = ez > 0.f ? ez : 0.2f * ez;
            ex = __expf(e);
        }
        exsum += ex;
        for (int j = 0; j < m; j++) {
            int sj   = __shfl_sync(0xFFFFFFFFu, s, j);
            float xj = __shfl_sync(0xFFFFFFFFu, ex, j);
            float4 h = *(const float4*)&g_hs[(size_t)sj * 128 + lane * 4];
            acc.x += h.x * xj; acc.y += h.y * xj;
            acc.z += h.z * xj; acc.w += h.w * xj;
        }
    }
    #pragma unroll
    for (int o = 16; o; o >>= 1) exsum += __shfl_xor_sync(0xFFFFFFFFu, exsum, o);
    float inv = exsum > 0.f ? 1.f / exsum : 0.f;
    float4 l  = *(const float4*)&g_lin[(size_t)gw * 128 + lane * 4];
    float4 bb = *(const float4*)&b[lane * 4];
    float4 lb = *(const float4*)&Lb[lane * 4];
    float4 r;
    r.x = fmaxf(acc.x * inv + bb.x + l.x + lb.x, 0.f);
    r.y = fmaxf(acc.y * inv + bb.y + l.y + lb.y, 0.f);
    r.z = fmaxf(acc.z * inv + bb.z + l.z + lb.z, 0.f);
    r.w = fmaxf(acc.w * inv + bb.w + l.w + lb.w, 0.f);
    // split h to bf16 hi/lo images for the next GEMM (fp32 h not needed elsewhere)
    ushort4 h4, l4;
    split_bf16(r.x, h4.x, l4.x); split_bf16(r.y, h4.y, l4.y);
    split_bf16(r.z, h4.z, l4.z); split_bf16(r.w, h4.w, l4.w);
    *(ushort4*)&g_ahi[(size_t)gw * 128 + lane * 4] = h4;
    *(ushort4*)&g_alo[(size_t)gw * 128 + lane * 4] = l4;
    // fused attention dots for the next stage
    float4 a4 = *(const float4*)&wa[lane * 4];
    float sa = r.x * a4.x + r.y * a4.y + r.z * a4.z + r.w * a4.w;
    float sb = 0.f;
    if (eb) {
        float4 b4 = *(const float4*)&wb[lane * 4];
        sb = r.x * b4.x + r.y * b4.y + r.z * b4.z + r.w * b4.w;
    }
    #pragma unroll
    for (int o = 16; o; o >>= 1) {
        sa += __shfl_xor_sync(0xFFFFFFFFu, sa, o);
        sb += __shfl_xor_sync(0xFFFFFFFFu, sb, o);
    }
    if (lane == 0) {
        ea[gw] = sa;
        if (eb) eb[gw] = sb;
    }
}

__global__ void __launch_bounds__(256) agg_pf_kernel(const float* __restrict__ bt,
                                                     float* __restrict__ out) {
    int gw = (blockIdx.x * blockDim.x + threadIdx.x) >> 5;
    int lane = threadIdx.x & 31;
    if (gw >= N_FP) return;
    int start = g_off_fp[gw];
    int end   = g_off_fp[gw + 1];
    float edd = g_edfp[gw];
    float2 acc = make_float2(0.f, 0.f);
    float exsum = 0.f;
    for (int base = start; base < end; base += 32) {
        int m = end - base; if (m > 32) m = 32;
        int s = 0; float ex = 0.f;
        if (lane < m) {
            s = g_srt_fp[base + lane];
            float ez = g_es3[s] + edd;
            float e = ez > 0.f ? ez : 0.2f * ez;
            ex = __expf(e);
        }
        exsum += ex;
        for (int j = 0; j < m; j++) {
            int sj   = __shfl_sync(0xFFFFFFFFu, s, j);
            float xj = __shfl_sync(0xFFFFFFFFu, ex, j);
            float2 h = *(const float2*)&g_hs[(size_t)sj * 64 + lane * 2];
            acc.x += h.x * xj; acc.y += h.y * xj;
        }
    }
    #pragma unroll
    for (int o = 16; o; o >>= 1) exsum += __shfl_xor_sync(0xFFFFFFFFu, exsum, o);
    float inv = exsum > 0.f ? 1.f / exsum : 0.f;
    float2 bb = *(const float2*)&bt[lane * 2];
    *(float2*)&out[(size_t)gw * 64 + lane * 2] = make_float2(acc.x * inv + bb.x,
                                                             acc.y * inv + bb.y);
}

// ---------------- launch ----------------
extern "C" void kernel_launch(void* const* d_in, const int* in_sizes, int n_in,
                              void* d_out, int out_size) {
    const float* x_pano = (const float*)d_in[0];
    const float* x_fp   = (const float*)d_in[1];
    const float* Ws0 = (const float*)d_in[2];
    const float* Wd0 = (const float*)d_in[3];
    const float* as0 = (const float*)d_in[4];
    const float* ad0 = (const float*)d_in[5];
    const float* b0  = (const float*)d_in[6];
    const float* Lw0 = (const float*)d_in[7];
    const float* Lb0 = (const float*)d_in[8];
    const float* Ws1 = (const float*)d_in[9];
    const float* Wd1 = (const float*)d_in[10];
    const float* as1 = (const float*)d_in[11];
    const float* ad1 = (const float*)d_in[12];
    const float* b1  = (const float*)d_in[13];
    const float* Lw1 = (const float*)d_in[14];
    const float* Lb1 = (const float*)d_in[15];
    const float* Wts = (const float*)d_in[16];
    const float* Wtd = (const float*)d_in[17];
    const float* ats = (const float*)d_in[18];
    const float* atd = (const float*)d_in[19];
    const float* bt  = (const float*)d_in[20];
    const int* edge_pp = (const int*)d_in[21];
    const int* pf_src  = (const int*)d_in[22];
    const int* pf_dst  = (const int*)d_in[23];
    const int* pp_src = edge_pp;
    const int* pp_dst = edge_pp + E_PP;

    float *p_hs, *p_lin, *p_es, *p_ed, *p_es2, *p_ed2, *p_es3, *p_edfp, *p_wc;
    cudaGetSymbolAddress((void**)&p_hs,   g_hs);
    cudaGetSymbolAddress((void**)&p_lin,  g_lin);
    cudaGetSymbolAddress((void**)&p_es,   g_es);
    cudaGetSymbolAddress((void**)&p_ed,   g_ed);
    cudaGetSymbolAddress((void**)&p_es2,  g_es2);
    cudaGetSymbolAddress((void**)&p_ed2,  g_ed2);
    cudaGetSymbolAddress((void**)&p_es3,  g_es3);
    cudaGetSymbolAddress((void**)&p_edfp, g_edfp);
    cudaGetSymbolAddress((void**)&p_wc,   g_wc);
    ushort_t *p_ahi, *p_alo, *p_b0hi, *p_b0lo, *p_b1hi, *p_b1lo, *p_bthi, *p_btlo;
    cudaGetSymbolAddress((void**)&p_ahi,  g_ahi);
    cudaGetSymbolAddress((void**)&p_alo,  g_alo);
    cudaGetSymbolAddress((void**)&p_b0hi, g_wb0hi);
    cudaGetSymbolAddress((void**)&p_b0lo, g_wb0lo);
    cudaGetSymbolAddress((void**)&p_b1hi, g_wb1hi);
    cudaGetSymbolAddress((void**)&p_b1lo, g_wb1lo);
    cudaGetSymbolAddress((void**)&p_bthi, g_wbthi);
    cudaGetSymbolAddress((void**)&p_btlo, g_wbtlo);

    const int TC_BLKS = (N_PANO + 127) / 128;        // 391
    const int EALL_BLKS = (E_PP + E_PF + 255) / 256; // 3321

    // ---- weight prep + CSR build ----
    prep_b_kernel<<<288, 256>>>(Ws0, Lw0, Ws1, Lw1, Wts);
    zero_cnt_kernel<<<(N_PANO + N_FP + 255) / 256, 256>>>();
    hist_kernel<<<EALL_BLKS, 256>>>(pp_dst, pf_dst);
    scan_kernel<<<2, 1024>>>();
    scatter_kernel<<<EALL_BLKS, 256>>>(pp_src, pp_dst, pf_src, pf_dst);
    compose_kernel<<<3, 256>>>(Ws0, as0, Wd0, ad0, Ws1, as1, Wd1, ad1, Wts, ats, Wtd, atd);

    // ---- layer 0 ----
    gemv2s_kernel<<<6250, 256>>>(x_pano, p_wc + 0, p_wc + 128, p_es, p_ed, N_PANO);
    mmagemm_kernel<128><<<dim3(TC_BLKS, 2), 256>>>(p_ahi, p_alo, p_b0hi, p_b0lo,
                                                   p_hs, p_lin, N_PANO);
    agg_pp_kernel<<<6250, 256>>>(b0, Lb0, p_es, p_ed, p_wc + 256, p_wc + 384, p_es2, p_ed2);

    // ---- layer 1 ----
    mmagemm_kernel<128><<<dim3(TC_BLKS, 2), 256>>>(p_ahi, p_alo, p_b1hi, p_b1lo,
                                                   p_hs, p_lin, N_PANO);
    agg_pp_kernel<<<6250, 256>>>(b1, Lb1, p_es2, p_ed2, p_wc + 512, (const float*)0,
                                 p_es3, (float*)0);

    // ---- translate pano -> footprint ----
    mmagemm_kernel<64><<<dim3(TC_BLKS, 1), 256>>>(p_ahi, p_alo, p_bthi, p_btlo,
                                                  p_hs, (float*)0, N_PANO);
    gemv1_64_kernel<<<1250, 256>>>(x_fp, p_wc + 640, p_edfp, N_FP);
    agg_pf_kernel<<<1250, 256>>>(bt, (float*)d_out);
}

// round 7
// speedup vs baseline: 1.9490x; 1.2844x over previous
#include <cuda_runtime.h>
#include <cuda_bf16.h>
#include <math.h>
#include <stdint.h>
#include <string.h>

#define N_PANO 50000
#define N_FP   10000
#define HID    128
#define E_PP   800000
#define E_PF   50000

#define SCAN_BPP 49   // ceil(50000/1024)
#define SCAN_BFP 10   // ceil(10000/1024)
#define SCAN_BLKS (SCAN_BPP + SCAN_BFP)

typedef unsigned short ushort_t;

// ---------------- device scratch (static, no allocation) ----------------
__device__ float g_hs[N_PANO * HID];
__device__ float g_lin[N_PANO * HID];
__device__ float g_es[N_PANO];
__device__ float g_ed[N_PANO];
__device__ float g_es2[N_PANO];
__device__ float g_ed2[N_PANO];
__device__ float g_es3[N_PANO];
__device__ float g_edfp[N_FP];
__device__ float g_wc[704];
// split-bf16 activation images (reused layer0 -> layer1 -> translate)
__device__ ushort_t g_ahi[N_PANO * 128];
__device__ ushort_t g_alo[N_PANO * 128];
// split-bf16 weight images, [N][K] row-major (B col-major for mma.row.col)
__device__ ushort_t g_wb0hi[256 * 128], g_wb0lo[256 * 128];
__device__ ushort_t g_wb1hi[256 * 128], g_wb1lo[256 * 128];
__device__ ushort_t g_wbthi[64 * 128],  g_wbtlo[64 * 128];
// CSR build
__device__ int g_cnt[N_PANO];
__device__ int g_off[N_PANO + 1];
__device__ int g_cur[N_PANO];
__device__ int g_srt[E_PP];
__device__ int g_cnt_fp[N_FP];
__device__ int g_off_fp[N_FP + 1];
__device__ int g_cur_fp[N_FP];
__device__ int g_srt_fp[E_PF];
__device__ int g_bsum[SCAN_BLKS];
__device__ int g_boff[SCAN_BLKS];

// ---------------- helpers ----------------
__device__ __forceinline__ uint32_t smem_u32(const void* p) {
    uint32_t a;
    asm("{ .reg .u64 t; cvta.to.shared.u64 t, %1; cvt.u32.u64 %0, t; }" : "=r"(a) : "l"(p));
    return a;
}
__device__ __forceinline__ void ldsm_x4(uint32_t* r, uint32_t addr) {
    asm volatile("ldmatrix.sync.aligned.m8n8.x4.shared.b16 {%0,%1,%2,%3}, [%4];"
                 : "=r"(r[0]), "=r"(r[1]), "=r"(r[2]), "=r"(r[3]) : "r"(addr));
}
__device__ __forceinline__ void ldsm_x2(uint32_t* r, uint32_t addr) {
    asm volatile("ldmatrix.sync.aligned.m8n8.x2.shared.b16 {%0,%1}, [%2];"
                 : "=r"(r[0]), "=r"(r[1]) : "r"(addr));
}
__device__ __forceinline__ void mma16816(float* d, const uint32_t* a, const uint32_t* b) {
    asm volatile("mma.sync.aligned.m16n8k16.row.col.f32.bf16.bf16.f32 "
                 "{%0,%1,%2,%3}, {%4,%5,%6,%7}, {%8,%9}, {%0,%1,%2,%3};"
                 : "+f"(d[0]), "+f"(d[1]), "+f"(d[2]), "+f"(d[3])
                 : "r"(a[0]), "r"(a[1]), "r"(a[2]), "r"(a[3]), "r"(b[0]), "r"(b[1]));
}
__device__ __forceinline__ void split_bf16(float v, ushort_t& h, ushort_t& l) {
    __nv_bfloat16 hb = __float2bfloat16(v);
    float r = v - __bfloat162float(hb);
    __nv_bfloat16 lb = __float2bfloat16(r);
    memcpy(&h, &hb, 2); memcpy(&l, &lb, 2);
}

// ---------------- weight prep: split to bf16 hi/lo, [N][K] row-major ----------------
__global__ void prep_b_kernel(const float* __restrict__ Ws0, const float* __restrict__ Lw0,
                              const float* __restrict__ Ws1, const float* __restrict__ Lw1,
                              const float* __restrict__ Wts) {
    int idx = blockIdx.x * blockDim.x + threadIdx.x;   // 73728 total
    ushort_t *ih, *il;
    int n, k;
    float v;
    if (idx < 32768) {
        n = idx >> 7; k = idx & 127;
        v = (n < 128) ? Ws0[k * 128 + n] : Lw0[k * 128 + (n - 128)];
        ih = g_wb0hi; il = g_wb0lo;
    } else if (idx < 65536) {
        int e = idx - 32768;
        n = e >> 7; k = e & 127;
        v = (n < 128) ? Ws1[k * 128 + n] : Lw1[k * 128 + (n - 128)];
        ih = g_wb1hi; il = g_wb1lo;
    } else if (idx < 73728) {
        int e = idx - 65536;
        n = e >> 7; k = e & 127;
        v = Wts[k * 64 + n];
        ih = g_wbthi; il = g_wbtlo;
    } else return;
    ushort_t h, l;
    split_bf16(v, h, l);
    ih[n * 128 + k] = h;
    il[n * 128 + k] = l;
}

// ---------------- HMMA GEMM: C[M,NTOT] = A[M,128] @ W, split-bf16 3 terms ----------------
template<int NT>
__global__ void __launch_bounds__(256) mmagemm_kernel(
        const ushort_t* __restrict__ Ahi, const ushort_t* __restrict__ Alo,
        const ushort_t* __restrict__ Bhi, const ushort_t* __restrict__ Blo,
        float* __restrict__ C1, float* __restrict__ C2, int M) {
    constexpr int NTW = NT / 4;
    constexpr int NTILES = NTW / 8;
    __shared__ ushort_t As[2][128][40];
    __shared__ ushort_t Bs[2][NT][40];
    const int tid = threadIdx.x;
    const int wid = tid >> 5, lane = tid & 31;
    const int wm = wid >> 2, wn = wid & 3;
    const int m0 = blockIdx.x * 128;
    const int nb = blockIdx.y * 128;

    float d[4][NTILES][4];
    #pragma unroll
    for (int mt = 0; mt < 4; mt++)
        #pragma unroll
        for (int nt = 0; nt < NTILES; nt++)
            #pragma unroll
            for (int j = 0; j < 4; j++) d[mt][nt][j] = 0.f;

    #pragma unroll 1
    for (int k0 = 0; k0 < 128; k0 += 32) {
        #pragma unroll
        for (int l = 0; l < 2; l++) {
            int i = tid + l * 256;
            int r = i >> 2, s = i & 3;
            uint4 vh = make_uint4(0, 0, 0, 0), vl = make_uint4(0, 0, 0, 0);
            if (m0 + r < M) {
                vh = *(const uint4*)&Ahi[(size_t)(m0 + r) * 128 + k0 + s * 8];
                vl = *(const uint4*)&Alo[(size_t)(m0 + r) * 128 + k0 + s * 8];
            }
            *(uint4*)&As[0][r][s * 8] = vh;
            *(uint4*)&As[1][r][s * 8] = vl;
        }
        #pragma unroll
        for (int l = 0; l < (NT * 4) / 256; l++) {
            int i = tid + l * 256;
            int r = i >> 2, s = i & 3;
            *(uint4*)&Bs[0][r][s * 8] = *(const uint4*)&Bhi[(size_t)(nb + r) * 128 + k0 + s * 8];
            *(uint4*)&Bs[1][r][s * 8] = *(const uint4*)&Blo[(size_t)(nb + r) * 128 + k0 + s * 8];
        }
        __syncthreads();
        #pragma unroll
        for (int kk = 0; kk < 32; kk += 16) {
            uint32_t ah[4][4], al[4][4], bh[NTILES][2], bl[NTILES][2];
            #pragma unroll
            for (int mt = 0; mt < 4; mt++) {
                int ar = wm * 64 + mt * 16 + (lane & 15);
                int ac = kk + (lane >> 4) * 8;
                ldsm_x4(ah[mt], smem_u32(&As[0][ar][ac]));
                ldsm_x4(al[mt], smem_u32(&As[1][ar][ac]));
            }
            #pragma unroll
            for (int nt = 0; nt < NTILES; nt++) {
                int l16 = lane & 15;
                int br = wn * NTW + nt * 8 + (l16 & 7);
                int bc = kk + (l16 >> 3) * 8;
                ldsm_x2(bh[nt], smem_u32(&Bs[0][br][bc]));
                ldsm_x2(bl[nt], smem_u32(&Bs[1][br][bc]));
            }
            #pragma unroll
            for (int mt = 0; mt < 4; mt++)
                #pragma unroll
                for (int nt = 0; nt < NTILES; nt++) {
                    mma16816(d[mt][nt], ah[mt], bh[nt]);
                    mma16816(d[mt][nt], al[mt], bh[nt]);
                    mma16816(d[mt][nt], ah[mt], bl[nt]);
                }
        }
        __syncthreads();
    }
    float* C = (NT == 64 || blockIdx.y == 0) ? C1 : C2;
    const int cstride = (NT == 64) ? 64 : 128;
    #pragma unroll
    for (int mt = 0; mt < 4; mt++) {
        int r0 = m0 + wm * 64 + mt * 16 + (lane >> 2);
        #pragma unroll
        for (int nt = 0; nt < NTILES; nt++) {
            int c = wn * NTW + nt * 8 + (lane & 3) * 2;
            if (r0 < M)
                *(float2*)&C[(size_t)r0 * cstride + c] = make_float2(d[mt][nt][0], d[mt][nt][1]);
            if (r0 + 8 < M)
                *(float2*)&C[(size_t)(r0 + 8) * cstride + c] = make_float2(d[mt][nt][2], d[mt][nt][3]);
        }
    }
}

// ---------------- compose: w = W @ a  (tiny) ----------------
__global__ void compose_kernel(const float* __restrict__ Ws0, const float* __restrict__ as0,
                               const float* __restrict__ Wd0, const float* __restrict__ ad0,
                               const float* __restrict__ Ws1, const float* __restrict__ as1,
                               const float* __restrict__ Wd1, const float* __restrict__ ad1,
                               const float* __restrict__ Wts, const float* __restrict__ ats,
                               const float* __restrict__ Wtd, const float* __restrict__ atd) {
    int b = blockIdx.x, t = threadIdx.x;
    if (b == 0) {
        if (t < 128) {
            float s = 0.f;
            for (int n = 0; n < 128; n++) s += Ws0[t * 128 + n] * as0[n];
            g_wc[t] = s;
        } else {
            int i = t - 128; float s = 0.f;
            for (int n = 0; n < 128; n++) s += Wd0[i * 128 + n] * ad0[n];
            g_wc[128 + i] = s;
        }
    } else if (b == 1) {
        if (t < 128) {
            float s = 0.f;
            for (int n = 0; n < 128; n++) s += Ws1[t * 128 + n] * as1[n];
            g_wc[256 + t] = s;
        } else {
            int i = t - 128; float s = 0.f;
            for (int n = 0; n < 128; n++) s += Wd1[i * 128 + n] * ad1[n];
            g_wc[384 + i] = s;
        }
    } else {
        if (t < 128) {
            float s = 0.f;
            for (int n = 0; n < 64; n++) s += Wts[t * 64 + n] * ats[n];
            g_wc[512 + t] = s;
        } else if (t < 192) {
            int i = t - 128; float s = 0.f;
            for (int n = 0; n < 64; n++) s += Wtd[i * 64 + n] * atd[n];
            g_wc[640 + i] = s;
        }
    }
}

// ---------------- CSR build kernels ----------------
__global__ void zero_cnt_kernel() {
    int i = blockIdx.x * blockDim.x + threadIdx.x;
    if (i < N_PANO) g_cnt[i] = 0;
    else if (i < N_PANO + N_FP) g_cnt_fp[i - N_PANO] = 0;
}

__global__ void hist_kernel(const int* __restrict__ dst_pp, const int* __restrict__ dst_pf) {
    int i = blockIdx.x * blockDim.x + threadIdx.x;
    if (i < E_PP) atomicAdd(&g_cnt[dst_pp[i]], 1);
    else if (i < E_PP + E_PF) atomicAdd(&g_cnt_fp[dst_pf[i - E_PP]], 1);
}

// ---- 3-phase parallel scan ----
// scan1: per-block tile scan (1024 elems / block via 256 threads x int4)
__global__ void __launch_bounds__(256) scan1_kernel() {
    __shared__ int woff[9];
    int blk = blockIdx.x;
    bool fp = blk >= SCAN_BPP;
    const int N = fp ? N_FP : N_PANO;
    const int* cnt = fp ? g_cnt_fp : g_cnt;
    int* off = fp ? g_off_fp : g_off;
    int base = (fp ? blk - SCAN_BPP : blk) * 1024;
    int t = threadIdx.x;
    int lane = t & 31, wid = t >> 5;
    int idx = base + t * 4;
    int4 v = make_int4(0, 0, 0, 0);
    if (idx < N) v = *(const int4*)&cnt[idx];
    int s0 = v.x, s1 = v.x + v.y, s2 = s1 + v.z, tot = s2 + v.w;
    // warp inclusive scan of tot
    int inc = tot;
    #pragma unroll
    for (int o = 1; o < 32; o <<= 1) {
        int n = __shfl_up_sync(0xFFFFFFFFu, inc, o);
        if (lane >= o) inc += n;
    }
    if (lane == 31) woff[wid] = inc;
    __syncthreads();
    if (t == 0) {
        int run = 0;
        #pragma unroll
        for (int j = 0; j < 8; j++) { int x = woff[j]; woff[j] = run; run += x; }
        g_bsum[blk] = run;
    }
    __syncthreads();
    int exc = woff[wid] + inc - tot;   // exclusive prefix (local to tile)
    if (idx < N)
        *(int4*)&off[idx] = make_int4(exc, exc + s0, exc + s1, exc + s2);
}

// scan2: scan the per-block totals (one tiny block)
__global__ void scan2_kernel() {
    __shared__ int sb[SCAN_BLKS];
    int t = threadIdx.x;
    if (t < SCAN_BLKS) sb[t] = g_bsum[t];
    __syncthreads();
    if (t == 0) {
        int run = 0;
        #pragma unroll
        for (int j = 0; j < SCAN_BPP; j++) { g_boff[j] = run; run += sb[j]; }
        g_off[N_PANO] = run;
    } else if (t == 1) {
        int run = 0;
        #pragma unroll
        for (int j = SCAN_BPP; j < SCAN_BLKS; j++) { g_boff[j] = run; run += sb[j]; }
        g_off_fp[N_FP] = run;
    }
}

// scan3: add block offsets, materialize cur
__global__ void __launch_bounds__(256) scan3_kernel() {
    int blk = blockIdx.x;
    bool fp = blk >= SCAN_BPP;
    const int N = fp ? N_FP : N_PANO;
    int* off = fp ? g_off_fp : g_off;
    int* cur = fp ? g_cur_fp : g_cur;
    int base = (fp ? blk - SCAN_BPP : blk) * 1024;
    int idx = base + threadIdx.x * 4;
    if (idx >= N) return;
    int bo = g_boff[blk];
    int4 o = *(const int4*)&off[idx];
    o.x += bo; o.y += bo; o.z += bo; o.w += bo;
    *(int4*)&off[idx] = o;
    *(int4*)&cur[idx] = o;
}

__global__ void scatter_kernel(const int* __restrict__ src_pp, const int* __restrict__ dst_pp,
                               const int* __restrict__ src_pf, const int* __restrict__ dst_pf) {
    int i = blockIdx.x * blockDim.x + threadIdx.x;
    if (i < E_PP) {
        int pos = atomicAdd(&g_cur[dst_pp[i]], 1);
        g_srt[pos] = src_pp[i];
    } else if (i < E_PP + E_PF) {
        int j = i - E_PP;
        int pos = atomicAdd(&g_cur_fp[dst_pf[j]], 1);
        g_srt_fp[pos] = src_pf[j];
    }
}

// ---------------- GEMV (layer 0) + fused bf16 split of x_pano ----------------
__global__ void gemv2s_kernel(const float* __restrict__ X, const float* __restrict__ wa,
                              const float* __restrict__ wb,
                              float* __restrict__ ea, float* __restrict__ eb, int M) {
    int gw = (blockIdx.x * blockDim.x + threadIdx.x) >> 5;
    int lane = threadIdx.x & 31;
    if (gw >= M) return;
    float4 x = *(const float4*)&X[(size_t)gw * 128 + lane * 4];
    ushort4 h4, l4;
    split_bf16(x.x, h4.x, l4.x); split_bf16(x.y, h4.y, l4.y);
    split_bf16(x.z, h4.z, l4.z); split_bf16(x.w, h4.w, l4.w);
    *(ushort4*)&g_ahi[(size_t)gw * 128 + lane * 4] = h4;
    *(ushort4*)&g_alo[(size_t)gw * 128 + lane * 4] = l4;
    float4 a = *(const float4*)&wa[lane * 4];
    float4 b = *(const float4*)&wb[lane * 4];
    float sa = x.x * a.x + x.y * a.y + x.z * a.z + x.w * a.w;
    float sb = x.x * b.x + x.y * b.y + x.z * b.z + x.w * b.w;
    #pragma unroll
    for (int o = 16; o; o >>= 1) {
        sa += __shfl_xor_sync(0xFFFFFFFFu, sa, o);
        sb += __shfl_xor_sync(0xFFFFFFFFu, sb, o);
    }
    if (lane == 0) { ea[gw] = sa; eb[gw] = sb; }
}

__global__ void gemv1_64_kernel(const float* __restrict__ X, const float* __restrict__ w,
                                float* __restrict__ out, int M) {
    int gw = (blockIdx.x * blockDim.x + threadIdx.x) >> 5;
    int lane = threadIdx.x & 31;
    if (gw >= M) return;
    float2 x = *(const float2*)&X[(size_t)gw * 64 + lane * 2];
    float2 a = *(const float2*)&w[lane * 2];
    float s = x.x * a.x + x.y * a.y;
    #pragma unroll
    for (int o = 16; o; o >>= 1) s += __shfl_xor_sync(0xFFFFFFFFu, s, o);
    if (lane == 0) out[gw] = s;
}

// ---------------- CSR aggregation + fused finalize + next-stage dots + bf16 split ----------------
__global__ void __launch_bounds__(256) agg_pp_kernel(const float* __restrict__ b,
                                                     const float* __restrict__ Lb,
                                                     const float* __restrict__ es_in,
                                                     const float* __restrict__ ed_in,
                                                     const float* __restrict__ wa,
                                                     const float* __restrict__ wb,
                                                     float* __restrict__ ea,
                                                     float* __restrict__ eb) {
    int gw = (blockIdx.x * blockDim.x + threadIdx.x) >> 5;
    int lane = threadIdx.x & 31;
    if (gw >= N_PANO) return;
    int start = g_off[gw];
    int end   = g_off[gw + 1];
    float edd = ed_in[gw];
    float4 acc = make_float4(0.f, 0.f, 0.f, 0.f);
    float exsum = 0.f;
    for (int base = start; base < end; base += 32) {
        int m = end - base; if (m > 32) m = 32;
        int s = 0; float ex = 0.f;
        if (lane < m) {
            s = g_srt[base + lane];
            float ez = es_in[s] + edd;
            float e = ez > 0.f ? ez : 0.2f * ez;
            ex = __expf(e);
        }
        exsum += ex;
        for (int j = 0; j < m; j++) {
            int sj   = __shfl_sync(0xFFFFFFFFu, s, j);
            float xj = __shfl_sync(0xFFFFFFFFu, ex, j);
            float4 h = *(const float4*)&g_hs[(size_t)sj * 128 + lane * 4];
            acc.x += h.x * xj; acc.y += h.y * xj;
            acc.z += h.z * xj; acc.w += h.w * xj;
        }
    }
    #pragma unroll
    for (int o = 16; o; o >>= 1) exsum += __shfl_xor_sync(0xFFFFFFFFu, exsum, o);
    float inv = exsum > 0.f ? 1.f / exsum : 0.f;
    float4 l  = *(const float4*)&g_lin[(size_t)gw * 128 + lane * 4];
    float4 bb = *(const float4*)&b[lane * 4];
    float4 lb = *(const float4*)&Lb[lane * 4];
    float4 r;
    r.x = fmaxf(acc.x * inv + bb.x + l.x + lb.x, 0.f);
    r.y = fmaxf(acc.y * inv + bb.y + l.y + lb.y, 0.f);
    r.z = fmaxf(acc.z * inv + bb.z + l.z + lb.z, 0.f);
    r.w = fmaxf(acc.w * inv + bb.w + l.w + lb.w, 0.f);
    ushort4 h4, l4;
    split_bf16(r.x, h4.x, l4.x); split_bf16(r.y, h4.y, l4.y);
    split_bf16(r.z, h4.z, l4.z); split_bf16(r.w, h4.w, l4.w);
    *(ushort4*)&g_ahi[(size_t)gw * 128 + lane * 4] = h4;
    *(ushort4*)&g_alo[(size_t)gw * 128 + lane * 4] = l4;
    float4 a4 = *(const float4*)&wa[lane * 4];
    float sa = r.x * a4.x + r.y * a4.y + r.z * a4.z + r.w * a4.w;
    float sb = 0.f;
    if (eb) {
        float4 b4 = *(const float4*)&wb[lane * 4];
        sb = r.x * b4.x + r.y * b4.y + r.z * b4.z + r.w * b4.w;
    }
    #pragma unroll
    for (int o = 16; o; o >>= 1) {
        sa += __shfl_xor_sync(0xFFFFFFFFu, sa, o);
        sb += __shfl_xor_sync(0xFFFFFFFFu, sb, o);
    }
    if (lane == 0) {
        ea[gw] = sa;
        if (eb) eb[gw] = sb;
    }
}

__global__ void __launch_bounds__(256) agg_pf_kernel(const float* __restrict__ bt,
                                                     float* __restrict__ out) {
    int gw = (blockIdx.x * blockDim.x + threadIdx.x) >> 5;
    int lane = threadIdx.x & 31;
    if (gw >= N_FP) return;
    int start = g_off_fp[gw];
    int end   = g_off_fp[gw + 1];
    float edd = g_edfp[gw];
    float2 acc = make_float2(0.f, 0.f);
    float exsum = 0.f;
    for (int base = start; base < end; base += 32) {
        int m = end - base; if (m > 32) m = 32;
        int s = 0; float ex = 0.f;
        if (lane < m) {
            s = g_srt_fp[base + lane];
            float ez = g_es3[s] + edd;
            float e = ez > 0.f ? ez : 0.2f * ez;
            ex = __expf(e);
        }
        exsum += ex;
        for (int j = 0; j < m; j++) {
            int sj   = __shfl_sync(0xFFFFFFFFu, s, j);
            float xj = __shfl_sync(0xFFFFFFFFu, ex, j);
            float2 h = *(const float2*)&g_hs[(size_t)sj * 64 + lane * 2];
            acc.x += h.x * xj; acc.y += h.y * xj;
        }
    }
    #pragma unroll
    for (int o = 16; o; o >>= 1) exsum += __shfl_xor_sync(0xFFFFFFFFu, exsum, o);
    float inv = exsum > 0.f ? 1.f / exsum : 0.f;
    float2 bb = *(const float2*)&bt[lane * 2];
    *(float2*)&out[(size_t)gw * 64 + lane * 2] = make_float2(acc.x * inv + bb.x,
                                                             acc.y * inv + bb.y);
}

// ---------------- launch ----------------
extern "C" void kernel_launch(void* const* d_in, const int* in_sizes, int n_in,
                              void* d_out, int out_size) {
    const float* x_pano = (const float*)d_in[0];
    const float* x_fp   = (const float*)d_in[1];
    const float* Ws0 = (const float*)d_in[2];
    const float* Wd0 = (const float*)d_in[3];
    const float* as0 = (const float*)d_in[4];
    const float* ad0 = (const float*)d_in[5];
    const float* b0  = (const float*)d_in[6];
    const float* Lw0 = (const float*)d_in[7];
    const float* Lb0 = (const float*)d_in[8];
    const float* Ws1 = (const float*)d_in[9];
    const float* Wd1 = (const float*)d_in[10];
    const float* as1 = (const float*)d_in[11];
    const float* ad1 = (const float*)d_in[12];
    const float* b1  = (const float*)d_in[13];
    const float* Lw1 = (const float*)d_in[14];
    const float* Lb1 = (const float*)d_in[15];
    const float* Wts = (const float*)d_in[16];
    const float* Wtd = (const float*)d_in[17];
    const float* ats = (const float*)d_in[18];
    const float* atd = (const float*)d_in[19];
    const float* bt  = (const float*)d_in[20];
    const int* edge_pp = (const int*)d_in[21];
    const int* pf_src  = (const int*)d_in[22];
    const int* pf_dst  = (const int*)d_in[23];
    const int* pp_src = edge_pp;
    const int* pp_dst = edge_pp + E_PP;

    float *p_hs, *p_lin, *p_es, *p_ed, *p_es2, *p_ed2, *p_es3, *p_edfp, *p_wc;
    cudaGetSymbolAddress((void**)&p_hs,   g_hs);
    cudaGetSymbolAddress((void**)&p_lin,  g_lin);
    cudaGetSymbolAddress((void**)&p_es,   g_es);
    cudaGetSymbolAddress((void**)&p_ed,   g_ed);
    cudaGetSymbolAddress((void**)&p_es2,  g_es2);
    cudaGetSymbolAddress((void**)&p_ed2,  g_ed2);
    cudaGetSymbolAddress((void**)&p_es3,  g_es3);
    cudaGetSymbolAddress((void**)&p_edfp, g_edfp);
    cudaGetSymbolAddress((void**)&p_wc,   g_wc);
    ushort_t *p_ahi, *p_alo, *p_b0hi, *p_b0lo, *p_b1hi, *p_b1lo, *p_bthi, *p_btlo;
    cudaGetSymbolAddress((void**)&p_ahi,  g_ahi);
    cudaGetSymbolAddress((void**)&p_alo,  g_alo);
    cudaGetSymbolAddress((void**)&p_b0hi, g_wb0hi);
    cudaGetSymbolAddress((void**)&p_b0lo, g_wb0lo);
    cudaGetSymbolAddress((void**)&p_b1hi, g_wb1hi);
    cudaGetSymbolAddress((void**)&p_b1lo, g_wb1lo);
    cudaGetSymbolAddress((void**)&p_bthi, g_wbthi);
    cudaGetSymbolAddress((void**)&p_btlo, g_wbtlo);

    const int TC_BLKS = (N_PANO + 127) / 128;        // 391
    const int EALL_BLKS = (E_PP + E_PF + 255) / 256; // 3321

    // ---- weight prep + CSR build ----
    prep_b_kernel<<<288, 256>>>(Ws0, Lw0, Ws1, Lw1, Wts);
    zero_cnt_kernel<<<(N_PANO + N_FP + 255) / 256, 256>>>();
    hist_kernel<<<EALL_BLKS, 256>>>(pp_dst, pf_dst);
    scan1_kernel<<<SCAN_BLKS, 256>>>();
    scan2_kernel<<<1, 64>>>();
    scan3_kernel<<<SCAN_BLKS, 256>>>();
    scatter_kernel<<<EALL_BLKS, 256>>>(pp_src, pp_dst, pf_src, pf_dst);
    compose_kernel<<<3, 256>>>(Ws0, as0, Wd0, ad0, Ws1, as1, Wd1, ad1, Wts, ats, Wtd, atd);

    // ---- layer 0 ----
    gemv2s_kernel<<<6250, 256>>>(x_pano, p_wc + 0, p_wc + 128, p_es, p_ed, N_PANO);
    mmagemm_kernel<128><<<dim3(TC_BLKS, 2), 256>>>(p_ahi, p_alo, p_b0hi, p_b0lo,
                                                   p_hs, p_lin, N_PANO);
    agg_pp_kernel<<<6250, 256>>>(b0, Lb0, p_es, p_ed, p_wc + 256, p_wc + 384, p_es2, p_ed2);

    // ---- layer 1 ----
    mmagemm_kernel<128><<<dim3(TC_BLKS, 2), 256>>>(p_ahi, p_alo, p_b1hi, p_b1lo,
                                                   p_hs, p_lin, N_PANO);
    agg_pp_kernel<<<6250, 256>>>(b1, Lb1, p_es2, p_ed2, p_wc + 512, (const float*)0,
                                 p_es3, (float*)0);

    // ---- translate pano -> footprint ----
    mmagemm_kernel<64><<<dim3(TC_BLKS, 1), 256>>>(p_ahi, p_alo, p_bthi, p_btlo,
                                                  p_hs, (float*)0, N_PANO);
    gemv1_64_kernel<<<1250, 256>>>(x_fp, p_wc + 640, p_edfp, N_FP);
    agg_pf_kernel<<<1250, 256>>>(bt, (float*)d_out);
}

// round 8
// speedup vs baseline: 2.0697x; 1.0619x over previous
#include <cuda_runtime.h>
#include <cuda_bf16.h>
#include <cuda_fp16.h>
#include <math.h>
#include <stdint.h>
#include <string.h>

#define N_PANO 50000
#define N_FP   10000
#define HID    128
#define E_PP   800000
#define E_PF   50000

#define SCAN_BPP 49   // ceil(50000/1024)
#define SCAN_BFP 10   // ceil(10000/1024)
#define SCAN_BLKS (SCAN_BPP + SCAN_BFP)

typedef unsigned short ushort_t;

// ---------------- device scratch (static, no allocation) ----------------
__device__ ushort_t g_hsh[N_PANO * HID];   // hs in fp16 (gather payload)
__device__ float g_lin[N_PANO * HID];
__device__ float g_es[N_PANO];
__device__ float g_ed[N_PANO];
__device__ float g_es2[N_PANO];
__device__ float g_ed2[N_PANO];
__device__ float g_es3[N_PANO];
__device__ float g_edfp[N_FP];
__device__ float g_wc[704];
// split-bf16 activation images (reused layer0 -> layer1 -> translate)
__device__ ushort_t g_ahi[N_PANO * 128];
__device__ ushort_t g_alo[N_PANO * 128];
// split-bf16 weight images, [N][K] row-major (B col-major for mma.row.col)
__device__ ushort_t g_wb0hi[256 * 128], g_wb0lo[256 * 128];
__device__ ushort_t g_wb1hi[256 * 128], g_wb1lo[256 * 128];
__device__ ushort_t g_wbthi[64 * 128],  g_wbtlo[64 * 128];
// CSR build
__device__ int g_cnt[N_PANO];
__device__ int g_off[N_PANO + 1];
__device__ int g_cur[N_PANO];
__device__ int g_srt[E_PP];
__device__ int g_cnt_fp[N_FP];
__device__ int g_off_fp[N_FP + 1];
__device__ int g_cur_fp[N_FP];
__device__ int g_srt_fp[E_PF];
__device__ int g_bsum[SCAN_BLKS];
__device__ int g_boff[SCAN_BLKS];

// ---------------- helpers ----------------
__device__ __forceinline__ uint32_t smem_u32(const void* p) {
    uint32_t a;
    asm("{ .reg .u64 t; cvta.to.shared.u64 t, %1; cvt.u32.u64 %0, t; }" : "=r"(a) : "l"(p));
    return a;
}
__device__ __forceinline__ void ldsm_x4(uint32_t* r, uint32_t addr) {
    asm volatile("ldmatrix.sync.aligned.m8n8.x4.shared.b16 {%0,%1,%2,%3}, [%4];"
                 : "=r"(r[0]), "=r"(r[1]), "=r"(r[2]), "=r"(r[3]) : "r"(addr));
}
__device__ __forceinline__ void ldsm_x2(uint32_t* r, uint32_t addr) {
    asm volatile("ldmatrix.sync.aligned.m8n8.x2.shared.b16 {%0,%1}, [%2];"
                 : "=r"(r[0]), "=r"(r[1]) : "r"(addr));
}
__device__ __forceinline__ void mma16816(float* d, const uint32_t* a, const uint32_t* b) {
    asm volatile("mma.sync.aligned.m16n8k16.row.col.f32.bf16.bf16.f32 "
                 "{%0,%1,%2,%3}, {%4,%5,%6,%7}, {%8,%9}, {%0,%1,%2,%3};"
                 : "+f"(d[0]), "+f"(d[1]), "+f"(d[2]), "+f"(d[3])
                 : "r"(a[0]), "r"(a[1]), "r"(a[2]), "r"(a[3]), "r"(b[0]), "r"(b[1]));
}
__device__ __forceinline__ void split_bf16(float v, ushort_t& h, ushort_t& l) {
    __nv_bfloat16 hb = __float2bfloat16(v);
    float r = v - __bfloat162float(hb);
    __nv_bfloat16 lb = __float2bfloat16(r);
    memcpy(&h, &hb, 2); memcpy(&l, &lb, 2);
}

// ---------------- weight prep: split to bf16 hi/lo, [N][K] row-major ----------------
__global__ void prep_b_kernel(const float* __restrict__ Ws0, const float* __restrict__ Lw0,
                              const float* __restrict__ Ws1, const float* __restrict__ Lw1,
                              const float* __restrict__ Wts) {
    int idx = blockIdx.x * blockDim.x + threadIdx.x;   // 73728 total
    ushort_t *ih, *il;
    int n, k;
    float v;
    if (idx < 32768) {
        n = idx >> 7; k = idx & 127;
        v = (n < 128) ? Ws0[k * 128 + n] : Lw0[k * 128 + (n - 128)];
        ih = g_wb0hi; il = g_wb0lo;
    } else if (idx < 65536) {
        int e = idx - 32768;
        n = e >> 7; k = e & 127;
        v = (n < 128) ? Ws1[k * 128 + n] : Lw1[k * 128 + (n - 128)];
        ih = g_wb1hi; il = g_wb1lo;
    } else if (idx < 73728) {
        int e = idx - 65536;
        n = e >> 7; k = e & 127;
        v = Wts[k * 64 + n];
        ih = g_wbthi; il = g_wbtlo;
    } else return;
    ushort_t h, l;
    split_bf16(v, h, l);
    ih[n * 128 + k] = h;
    il[n * 128 + k] = l;
}

// ---------------- HMMA GEMM: C[M,NTOT] = A[M,128] @ W, split-bf16 3 terms ----------------
// hs half (C1h, fp16); lin half (C2, fp32) when NT==128 & blockIdx.y==1.
template<int NT>
__global__ void __launch_bounds__(256) mmagemm_kernel(
        const ushort_t* __restrict__ Ahi, const ushort_t* __restrict__ Alo,
        const ushort_t* __restrict__ Bhi, const ushort_t* __restrict__ Blo,
        ushort_t* __restrict__ C1h, float* __restrict__ C2, int M) {
    constexpr int NTW = NT / 4;
    constexpr int NTILES = NTW / 8;
    __shared__ ushort_t As[2][128][40];
    __shared__ ushort_t Bs[2][NT][40];
    const int tid = threadIdx.x;
    const int wid = tid >> 5, lane = tid & 31;
    const int wm = wid >> 2, wn = wid & 3;
    const int m0 = blockIdx.x * 128;
    const int nb = blockIdx.y * 128;

    float d[4][NTILES][4];
    #pragma unroll
    for (int mt = 0; mt < 4; mt++)
        #pragma unroll
        for (int nt = 0; nt < NTILES; nt++)
            #pragma unroll
            for (int j = 0; j < 4; j++) d[mt][nt][j] = 0.f;

    #pragma unroll 1
    for (int k0 = 0; k0 < 128; k0 += 32) {
        #pragma unroll
        for (int l = 0; l < 2; l++) {
            int i = tid + l * 256;
            int r = i >> 2, s = i & 3;
            uint4 vh = make_uint4(0, 0, 0, 0), vl = make_uint4(0, 0, 0, 0);
            if (m0 + r < M) {
                vh = *(const uint4*)&Ahi[(size_t)(m0 + r) * 128 + k0 + s * 8];
                vl = *(const uint4*)&Alo[(size_t)(m0 + r) * 128 + k0 + s * 8];
            }
            *(uint4*)&As[0][r][s * 8] = vh;
            *(uint4*)&As[1][r][s * 8] = vl;
        }
        #pragma unroll
        for (int l = 0; l < (NT * 4) / 256; l++) {
            int i = tid + l * 256;
            int r = i >> 2, s = i & 3;
            *(uint4*)&Bs[0][r][s * 8] = *(const uint4*)&Bhi[(size_t)(nb + r) * 128 + k0 + s * 8];
            *(uint4*)&Bs[1][r][s * 8] = *(const uint4*)&Blo[(size_t)(nb + r) * 128 + k0 + s * 8];
        }
        __syncthreads();
        #pragma unroll
        for (int kk = 0; kk < 32; kk += 16) {
            uint32_t ah[4][4], al[4][4], bh[NTILES][2], bl[NTILES][2];
            #pragma unroll
            for (int mt = 0; mt < 4; mt++) {
                int ar = wm * 64 + mt * 16 + (lane & 15);
                int ac = kk + (lane >> 4) * 8;
                ldsm_x4(ah[mt], smem_u32(&As[0][ar][ac]));
                ldsm_x4(al[mt], smem_u32(&As[1][ar][ac]));
            }
            #pragma unroll
            for (int nt = 0; nt < NTILES; nt++) {
                int l16 = lane & 15;
                int br = wn * NTW + nt * 8 + (l16 & 7);
                int bc = kk + (l16 >> 3) * 8;
                ldsm_x2(bh[nt], smem_u32(&Bs[0][br][bc]));
                ldsm_x2(bl[nt], smem_u32(&Bs[1][br][bc]));
            }
            #pragma unroll
            for (int mt = 0; mt < 4; mt++)
                #pragma unroll
                for (int nt = 0; nt < NTILES; nt++) {
                    mma16816(d[mt][nt], ah[mt], bh[nt]);
                    mma16816(d[mt][nt], al[mt], bh[nt]);
                    mma16816(d[mt][nt], ah[mt], bl[nt]);
                }
        }
        __syncthreads();
    }
    const bool to_half = (NT == 64) || (blockIdx.y == 0);
    const int cstride = (NT == 64) ? 64 : 128;
    #pragma unroll
    for (int mt = 0; mt < 4; mt++) {
        int r0 = m0 + wm * 64 + mt * 16 + (lane >> 2);
        #pragma unroll
        for (int nt = 0; nt < NTILES; nt++) {
            int c = wn * NTW + nt * 8 + (lane & 3) * 2;
            if (to_half) {
                if (r0 < M)
                    *reinterpret_cast<__half2*>(&C1h[(size_t)r0 * cstride + c]) =
                        __floats2half2_rn(d[mt][nt][0], d[mt][nt][1]);
                if (r0 + 8 < M)
                    *reinterpret_cast<__half2*>(&C1h[(size_t)(r0 + 8) * cstride + c]) =
                        __floats2half2_rn(d[mt][nt][2], d[mt][nt][3]);
            } else {
                if (r0 < M)
                    *(float2*)&C2[(size_t)r0 * cstride + c] = make_float2(d[mt][nt][0], d[mt][nt][1]);
                if (r0 + 8 < M)
                    *(float2*)&C2[(size_t)(r0 + 8) * cstride + c] = make_float2(d[mt][nt][2], d[mt][nt][3]);
            }
        }
    }
}

// ---------------- compose: w = W @ a  (tiny) ----------------
__global__ void compose_kernel(const float* __restrict__ Ws0, const float* __restrict__ as0,
                               const float* __restrict__ Wd0, const float* __restrict__ ad0,
                               const float* __restrict__ Ws1, const float* __restrict__ as1,
                               const float* __restrict__ Wd1, const float* __restrict__ ad1,
                               const float* __restrict__ Wts, const float* __restrict__ ats,
                               const float* __restrict__ Wtd, const float* __restrict__ atd) {
    int b = blockIdx.x, t = threadIdx.x;
    if (b == 0) {
        if (t < 128) {
            float s = 0.f;
            for (int n = 0; n < 128; n++) s += Ws0[t * 128 + n] * as0[n];
            g_wc[t] = s;
        } else {
            int i = t - 128; float s = 0.f;
            for (int n = 0; n < 128; n++) s += Wd0[i * 128 + n] * ad0[n];
            g_wc[128 + i] = s;
        }
    } else if (b == 1) {
        if (t < 128) {
            float s = 0.f;
            for (int n = 0; n < 128; n++) s += Ws1[t * 128 + n] * as1[n];
            g_wc[256 + t] = s;
        } else {
            int i = t - 128; float s = 0.f;
            for (int n = 0; n < 128; n++) s += Wd1[i * 128 + n] * ad1[n];
            g_wc[384 + i] = s;
        }
    } else {
        if (t < 128) {
            float s = 0.f;
            for (int n = 0; n < 64; n++) s += Wts[t * 64 + n] * ats[n];
            g_wc[512 + t] = s;
        } else if (t < 192) {
            int i = t - 128; float s = 0.f;
            for (int n = 0; n < 64; n++) s += Wtd[i * 64 + n] * atd[n];
            g_wc[640 + i] = s;
        }
    }
}

// ---------------- CSR build kernels ----------------
__global__ void zero_cnt_kernel() {
    int i = blockIdx.x * blockDim.x + threadIdx.x;
    if (i < N_PANO) g_cnt[i] = 0;
    else if (i < N_PANO + N_FP) g_cnt_fp[i - N_PANO] = 0;
}

__global__ void hist_kernel(const int* __restrict__ dst_pp, const int* __restrict__ dst_pf) {
    int i = blockIdx.x * blockDim.x + threadIdx.x;
    if (i < E_PP) atomicAdd(&g_cnt[dst_pp[i]], 1);
    else if (i < E_PP + E_PF) atomicAdd(&g_cnt_fp[dst_pf[i - E_PP]], 1);
}

// ---- 3-phase parallel scan ----
__global__ void __launch_bounds__(256) scan1_kernel() {
    __shared__ int woff[9];
    int blk = blockIdx.x;
    bool fp = blk >= SCAN_BPP;
    const int N = fp ? N_FP : N_PANO;
    const int* cnt = fp ? g_cnt_fp : g_cnt;
    int* off = fp ? g_off_fp : g_off;
    int base = (fp ? blk - SCAN_BPP : blk) * 1024;
    int t = threadIdx.x;
    int lane = t & 31, wid = t >> 5;
    int idx = base + t * 4;
    int4 v = make_int4(0, 0, 0, 0);
    if (idx < N) v = *(const int4*)&cnt[idx];
    int s0 = v.x, s1 = v.x + v.y, s2 = s1 + v.z, tot = s2 + v.w;
    int inc = tot;
    #pragma unroll
    for (int o = 1; o < 32; o <<= 1) {
        int n = __shfl_up_sync(0xFFFFFFFFu, inc, o);
        if (lane >= o) inc += n;
    }
    if (lane == 31) woff[wid] = inc;
    __syncthreads();
    if (t == 0) {
        int run = 0;
        #pragma unroll
        for (int j = 0; j < 8; j++) { int x = woff[j]; woff[j] = run; run += x; }
        g_bsum[blk] = run;
    }
    __syncthreads();
    int exc = woff[wid] + inc - tot;
    if (idx < N)
        *(int4*)&off[idx] = make_int4(exc, exc + s0, exc + s1, exc + s2);
}

__global__ void scan2_kernel() {
    __shared__ int sb[SCAN_BLKS];
    int t = threadIdx.x;
    if (t < SCAN_BLKS) sb[t] = g_bsum[t];
    __syncthreads();
    if (t == 0) {
        int run = 0;
        #pragma unroll
        for (int j = 0; j < SCAN_BPP; j++) { g_boff[j] = run; run += sb[j]; }
        g_off[N_PANO] = run;
    } else if (t == 1) {
        int run = 0;
        #pragma unroll
        for (int j = SCAN_BPP; j < SCAN_BLKS; j++) { g_boff[j] = run; run += sb[j]; }
        g_off_fp[N_FP] = run;
    }
}

__global__ void __launch_bounds__(256) scan3_kernel() {
    int blk = blockIdx.x;
    bool fp = blk >= SCAN_BPP;
    const int N = fp ? N_FP : N_PANO;
    int* off = fp ? g_off_fp : g_off;
    int* cur = fp ? g_cur_fp : g_cur;
    int base = (fp ? blk - SCAN_BPP : blk) * 1024;
    int idx = base + threadIdx.x * 4;
    if (idx >= N) return;
    int bo = g_boff[blk];
    int4 o = *(const int4*)&off[idx];
    o.x += bo; o.y += bo; o.z += bo; o.w += bo;
    *(int4*)&off[idx] = o;
    *(int4*)&cur[idx] = o;
}

__global__ void scatter_kernel(const int* __restrict__ src_pp, const int* __restrict__ dst_pp,
                               const int* __restrict__ src_pf, const int* __restrict__ dst_pf) {
    int i = blockIdx.x * blockDim.x + threadIdx.x;
    if (i < E_PP) {
        int pos = atomicAdd(&g_cur[dst_pp[i]], 1);
        g_srt[pos] = src_pp[i];
    } else if (i < E_PP + E_PF) {
        int j = i - E_PP;
        int pos = atomicAdd(&g_cur_fp[dst_pf[j]], 1);
        g_srt_fp[pos] = src_pf[j];
    }
}

// ---------------- GEMV (layer 0) + fused bf16 split of x_pano ----------------
__global__ void gemv2s_kernel(const float* __restrict__ X, const float* __restrict__ wa,
                              const float* __restrict__ wb,
                              float* __restrict__ ea, float* __restrict__ eb, int M) {
    int gw = (blockIdx.x * blockDim.x + threadIdx.x) >> 5;
    int lane = threadIdx.x & 31;
    if (gw >= M) return;
    float4 x = *(const float4*)&X[(size_t)gw * 128 + lane * 4];
    ushort4 h4, l4;
    split_bf16(x.x, h4.x, l4.x); split_bf16(x.y, h4.y, l4.y);
    split_bf16(x.z, h4.z, l4.z); split_bf16(x.w, h4.w, l4.w);
    *(ushort4*)&g_ahi[(size_t)gw * 128 + lane * 4] = h4;
    *(ushort4*)&g_alo[(size_t)gw * 128 + lane * 4] = l4;
    float4 a = *(const float4*)&wa[lane * 4];
    float4 b = *(const float4*)&wb[lane * 4];
    float sa = x.x * a.x + x.y * a.y + x.z * a.z + x.w * a.w;
    float sb = x.x * b.x + x.y * b.y + x.z * b.z + x.w * b.w;
    #pragma unroll
    for (int o = 16; o; o >>= 1) {
        sa += __shfl_xor_sync(0xFFFFFFFFu, sa, o);
        sb += __shfl_xor_sync(0xFFFFFFFFu, sb, o);
    }
    if (lane == 0) { ea[gw] = sa; eb[gw] = sb; }
}

__global__ void gemv1_64_kernel(const float* __restrict__ X, const float* __restrict__ w,
                                float* __restrict__ out, int M) {
    int gw = (blockIdx.x * blockDim.x + threadIdx.x) >> 5;
    int lane = threadIdx.x & 31;
    if (gw >= M) return;
    float2 x = *(const float2*)&X[(size_t)gw * 64 + lane * 2];
    float2 a = *(const float2*)&w[lane * 2];
    float s = x.x * a.x + x.y * a.y;
    #pragma unroll
    for (int o = 16; o; o >>= 1) s += __shfl_xor_sync(0xFFFFFFFFu, s, o);
    if (lane == 0) out[gw] = s;
}

// ---------------- CSR aggregation + fused finalize + next-stage dots + bf16 split ----------------
__global__ void __launch_bounds__(256) agg_pp_kernel(const float* __restrict__ b,
                                                     const float* __restrict__ Lb,
                                                     const float* __restrict__ es_in,
                                                     const float* __restrict__ ed_in,
                                                     const float* __restrict__ wa,
                                                     const float* __restrict__ wb,
                                                     float* __restrict__ ea,
                                                     float* __restrict__ eb) {
    int gw = (blockIdx.x * blockDim.x + threadIdx.x) >> 5;
    int lane = threadIdx.x & 31;
    if (gw >= N_PANO) return;
    int start = g_off[gw];
    int end   = g_off[gw + 1];
    float edd = ed_in[gw];
    float4 acc = make_float4(0.f, 0.f, 0.f, 0.f);
    float exsum = 0.f;
    for (int base = start; base < end; base += 32) {
        int m = end - base; if (m > 32) m = 32;
        int s = 0; float ex = 0.f;
        if (lane < m) {
            s = g_srt[base + lane];
            float ez = es_in[s] + edd;
            float e = ez > 0.f ? ez : 0.2f * ez;
            ex = __expf(e);
        }
        exsum += ex;
        for (int j = 0; j < m; j++) {
            int sj   = __shfl_sync(0xFFFFFFFFu, s, j);
            float xj = __shfl_sync(0xFFFFFFFFu, ex, j);
            uint2 hp = *(const uint2*)&g_hsh[(size_t)sj * 128 + lane * 4];
            float2 f0 = __half22float2(*reinterpret_cast<const __half2*>(&hp.x));
            float2 f1 = __half22float2(*reinterpret_cast<const __half2*>(&hp.y));
            acc.x += f0.x * xj; acc.y += f0.y * xj;
            acc.z += f1.x * xj; acc.w += f1.y * xj;
        }
    }
    #pragma unroll
    for (int o = 16; o; o >>= 1) exsum += __shfl_xor_sync(0xFFFFFFFFu, exsum, o);
    float inv = exsum > 0.f ? 1.f / exsum : 0.f;
    float4 l  = *(const float4*)&g_lin[(size_t)gw * 128 + lane * 4];
    float4 bb = *(const float4*)&b[lane * 4];
    float4 lb = *(const float4*)&Lb[lane * 4];
    float4 r;
    r.x = fmaxf(acc.x * inv + bb.x + l.x + lb.x, 0.f);
    r.y = fmaxf(acc.y * inv + bb.y + l.y + lb.y, 0.f);
    r.z = fmaxf(acc.z * inv + bb.z + l.z + lb.z, 0.f);
    r.w = fmaxf(acc.w * inv + bb.w + l.w + lb.w, 0.f);
    // split h to bf16 hi/lo images for the next GEMM
    ushort4 h4, l4;
    split_bf16(r.x, h4.x, l4.x); split_bf16(r.y, h4.y, l4.y);
    split_bf16(r.z, h4.z, l4.z); split_bf16(r.w, h4.w, l4.w);
    *(ushort4*)&g_ahi[(size_t)gw * 128 + lane * 4] = h4;
    *(ushort4*)&g_alo[(size_t)gw * 128 + lane * 4] = l4;
    // fused attention dots for the next stage
    float4 a4 = *(const float4*)&wa[lane * 4];
    float sa = r.x * a4.x + r.y * a4.y + r.z * a4.z + r.w * a4.w;
    float sb = 0.f;
    if (eb) {
        float4 b4 = *(const float4*)&wb[lane * 4];
        sb = r.x * b4.x + r.y * b4.y + r.z * b4.z + r.w * b4.w;
    }
    #pragma unroll
    for (int o = 16; o; o >>= 1) {
        sa += __shfl_xor_sync(0xFFFFFFFFu, sa, o);
        sb += __shfl_xor_sync(0xFFFFFFFFu, sb, o);
    }
    if (lane == 0) {
        ea[gw] = sa;
        if (eb) eb[gw] = sb;
    }
}

__global__ void __launch_bounds__(256) agg_pf_kernel(const float* __restrict__ bt,
                                                     float* __restrict__ out) {
    int gw = (blockIdx.x * blockDim.x + threadIdx.x) >> 5;
    int lane = threadIdx.x & 31;
    if (gw >= N_FP) return;
    int start = g_off_fp[gw];
    int end   = g_off_fp[gw + 1];
    float edd = g_edfp[gw];
    float2 acc = make_float2(0.f, 0.f);
    float exsum = 0.f;
    for (int base = start; base < end; base += 32) {
        int m = end - base; if (m > 32) m = 32;
        int s = 0; float ex = 0.f;
        if (lane < m) {
            s = g_srt_fp[base + lane];
            float ez = g_es3[s] + edd;
            float e = ez > 0.f ? ez : 0.2f * ez;
            ex = __expf(e);
        }
        exsum += ex;
        for (int j = 0; j < m; j++) {
            int sj   = __shfl_sync(0xFFFFFFFFu, s, j);
            float xj = __shfl_sync(0xFFFFFFFFu, ex, j);
            uint32_t hp = *(const uint32_t*)&g_hsh[(size_t)sj * 64 + lane * 2];
            float2 f = __half22float2(*reinterpret_cast<const __half2*>(&hp));
            acc.x += f.x * xj; acc.y += f.y * xj;
        }
    }
    #pragma unroll
    for (int o = 16; o; o >>= 1) exsum += __shfl_xor_sync(0xFFFFFFFFu, exsum, o);
    float inv = exsum > 0.f ? 1.f / exsum : 0.f;
    float2 bb = *(const float2*)&bt[lane * 2];
    *(float2*)&out[(size_t)gw * 64 + lane * 2] = make_float2(acc.x * inv + bb.x,
                                                             acc.y * inv + bb.y);
}

// ---------------- launch ----------------
extern "C" void kernel_launch(void* const* d_in, const int* in_sizes, int n_in,
                              void* d_out, int out_size) {
    const float* x_pano = (const float*)d_in[0];
    const float* x_fp   = (const float*)d_in[1];
    const float* Ws0 = (const float*)d_in[2];
    const float* Wd0 = (const float*)d_in[3];
    const float* as0 = (const float*)d_in[4];
    const float* ad0 = (const float*)d_in[5];
    const float* b0  = (const float*)d_in[6];
    const float* Lw0 = (const float*)d_in[7];
    const float* Lb0 = (const float*)d_in[8];
    const float* Ws1 = (const float*)d_in[9];
    const float* Wd1 = (const float*)d_in[10];
    const float* as1 = (const float*)d_in[11];
    const float* ad1 = (const float*)d_in[12];
    const float* b1  = (const float*)d_in[13];
    const float* Lw1 = (const float*)d_in[14];
    const float* Lb1 = (const float*)d_in[15];
    const float* Wts = (const float*)d_in[16];
    const float* Wtd = (const float*)d_in[17];
    const float* ats = (const float*)d_in[18];
    const float* atd = (const float*)d_in[19];
    const float* bt  = (const float*)d_in[20];
    const int* edge_pp = (const int*)d_in[21];
    const int* pf_src  = (const int*)d_in[22];
    const int* pf_dst  = (const int*)d_in[23];
    const int* pp_src = edge_pp;
    const int* pp_dst = edge_pp + E_PP;

    float *p_lin, *p_es, *p_ed, *p_es2, *p_ed2, *p_es3, *p_edfp, *p_wc;
    cudaGetSymbolAddress((void**)&p_lin,  g_lin);
    cudaGetSymbolAddress((void**)&p_es,   g_es);
    cudaGetSymbolAddress((void**)&p_ed,   g_ed);
    cudaGetSymbolAddress((void**)&p_es2,  g_es2);
    cudaGetSymbolAddress((void**)&p_ed2,  g_ed2);
    cudaGetSymbolAddress((void**)&p_es3,  g_es3);
    cudaGetSymbolAddress((void**)&p_edfp, g_edfp);
    cudaGetSymbolAddress((void**)&p_wc,   g_wc);
    ushort_t *p_hsh, *p_ahi, *p_alo, *p_b0hi, *p_b0lo, *p_b1hi, *p_b1lo, *p_bthi, *p_btlo;
    cudaGetSymbolAddress((void**)&p_hsh,  g_hsh);
    cudaGetSymbolAddress((void**)&p_ahi,  g_ahi);
    cudaGetSymbolAddress((void**)&p_alo,  g_alo);
    cudaGetSymbolAddress((void**)&p_b0hi, g_wb0hi);
    cudaGetSymbolAddress((void**)&p_b0lo, g_wb0lo);
    cudaGetSymbolAddress((void**)&p_b1hi, g_wb1hi);
    cudaGetSymbolAddress((void**)&p_b1lo, g_wb1lo);
    cudaGetSymbolAddress((void**)&p_bthi, g_wbthi);
    cudaGetSymbolAddress((void**)&p_btlo, g_wbtlo);

    const int TC_BLKS = (N_PANO + 127) / 128;        // 391
    const int EALL_BLKS = (E_PP + E_PF + 255) / 256; // 3321

    // ---- weight prep + CSR build ----
    prep_b_kernel<<<288, 256>>>(Ws0, Lw0, Ws1, Lw1, Wts);
    zero_cnt_kernel<<<(N_PANO + N_FP + 255) / 256, 256>>>();
    hist_kernel<<<EALL_BLKS, 256>>>(pp_dst, pf_dst);
    scan1_kernel<<<SCAN_BLKS, 256>>>();
    scan2_kernel<<<1, 64>>>();
    scan3_kernel<<<SCAN_BLKS, 256>>>();
    scatter_kernel<<<EALL_BLKS, 256>>>(pp_src, pp_dst, pf_src, pf_dst);
    compose_kernel<<<3, 256>>>(Ws0, as0, Wd0, ad0, Ws1, as1, Wd1, ad1, Wts, ats, Wtd, atd);

    // ---- layer 0 ----
    gemv2s_kernel<<<6250, 256>>>(x_pano, p_wc + 0, p_wc + 128, p_es, p_ed, N_PANO);
    mmagemm_kernel<128><<<dim3(TC_BLKS, 2), 256>>>(p_ahi, p_alo, p_b0hi, p_b0lo,
                                                   p_hsh, p_lin, N_PANO);
    agg_pp_kernel<<<6250, 256>>>(b0, Lb0, p_es, p_ed, p_wc + 256, p_wc + 384, p_es2, p_ed2);

    // ---- layer 1 ----
    mmagemm_kernel<128><<<dim3(TC_BLKS, 2), 256>>>(p_ahi, p_alo, p_b1hi, p_b1lo,
                                                   p_hsh, p_lin, N_PANO);
    agg_pp_kernel<<<6250, 256>>>(b1, Lb1, p_es2, p_ed2, p_wc + 512, (const float*)0,
                                 p_es3, (float*)0);

    // ---- translate pano -> footprint ----
    mmagemm_kernel<64><<<dim3(TC_BLKS, 1), 256>>>(p_ahi, p_alo, p_bthi, p_btlo,
                                                  p_hsh, (float*)0, N_PANO);
    gemv1_64_kernel<<<1250, 256>>>(x_fp, p_wc + 640, p_edfp, N_FP);
    agg_pf_kernel<<<1250, 256>>>(bt, (float*)d_out);
}

// round 9
// speedup vs baseline: 2.3019x; 1.1122x over previous
#include <cuda_runtime.h>
#include <cuda_bf16.h>
#include <cuda_fp16.h>
#include <math.h>
#include <stdint.h>
#include <string.h>

#define N_PANO 50000
#define N_FP   10000
#define HID    128
#define E_PP   800000
#define E_PF   50000

#define SCAN_BPP 49
#define SCAN_BFP 10
#define SCAN_BLKS (SCAN_BPP + SCAN_BFP)

#define GEMM_MBLKS 391        // ceil(50000/128)
#define EALL_BLKS  3321       // ceil(850000/256)

typedef unsigned short ushort_t;

// ---------------- device scratch (static, no allocation) ----------------
__device__ float    g_h[N_PANO * HID];      // fp32 activations (GEMM A input)
__device__ ushort_t g_hsh[N_PANO * HID];    // hs fp16 (gather payload)
__device__ ushort_t g_linh[N_PANO * HID];   // lin fp16
__device__ float g_es[N_PANO];
__device__ float g_ed[N_PANO];
__device__ float g_es2[N_PANO];
__device__ float g_ed2[N_PANO];
__device__ float g_es3[N_PANO];
__device__ float g_edfp[N_FP];
__device__ float g_wc[704];
// split-bf16 weight images, [N][K] row-major
__device__ ushort_t g_wb0hi[256 * 128], g_wb0lo[256 * 128];
__device__ ushort_t g_wb1hi[256 * 128], g_wb1lo[256 * 128];
__device__ ushort_t g_wbthi[64 * 128],  g_wbtlo[64 * 128];
// CSR build
__device__ int g_cnt[N_PANO];
__device__ int g_off[N_PANO + 1];
__device__ int g_cur[N_PANO];
__device__ int g_srt[E_PP];
__device__ int g_cnt_fp[N_FP];
__device__ int g_off_fp[N_FP + 1];
__device__ int g_cur_fp[N_FP];
__device__ int g_srt_fp[E_PF];
__device__ int g_bsum[SCAN_BLKS];

// ---------------- helpers ----------------
__device__ __forceinline__ uint32_t smem_u32(const void* p) {
    uint32_t a;
    asm("{ .reg .u64 t; cvta.to.shared.u64 t, %1; cvt.u32.u64 %0, t; }" : "=r"(a) : "l"(p));
    return a;
}
__device__ __forceinline__ void ldsm_x4(uint32_t* r, uint32_t addr) {
    asm volatile("ldmatrix.sync.aligned.m8n8.x4.shared.b16 {%0,%1,%2,%3}, [%4];"
                 : "=r"(r[0]), "=r"(r[1]), "=r"(r[2]), "=r"(r[3]) : "r"(addr));
}
__device__ __forceinline__ void ldsm_x2(uint32_t* r, uint32_t addr) {
    asm volatile("ldmatrix.sync.aligned.m8n8.x2.shared.b16 {%0,%1}, [%2];"
                 : "=r"(r[0]), "=r"(r[1]) : "r"(addr));
}
__device__ __forceinline__ void mma16816(float* d, const uint32_t* a, const uint32_t* b) {
    asm volatile("mma.sync.aligned.m16n8k16.row.col.f32.bf16.bf16.f32 "
                 "{%0,%1,%2,%3}, {%4,%5,%6,%7}, {%8,%9}, {%0,%1,%2,%3};"
                 : "+f"(d[0]), "+f"(d[1]), "+f"(d[2]), "+f"(d[3])
                 : "r"(a[0]), "r"(a[1]), "r"(a[2]), "r"(a[3]), "r"(b[0]), "r"(b[1]));
}
__device__ __forceinline__ void split_bf16(float v, ushort_t& h, ushort_t& l) {
    __nv_bfloat16 hb = __float2bfloat16(v);
    float r = v - __bfloat162float(hb);
    __nv_bfloat16 lb = __float2bfloat16(r);
    memcpy(&h, &hb, 2); memcpy(&l, &lb, 2);
}

// ---------------- GEMM body: C[M,NT*(grid.y)] = A_fp32[M,128] @ W, split-bf16 ----------------
template<int NT>
__device__ __forceinline__ void gemm_body(
        int bx, int by,
        const float* __restrict__ A,
        const ushort_t* __restrict__ Bhi, const ushort_t* __restrict__ Blo,
        ushort_t* __restrict__ C1h, ushort_t* __restrict__ C2h, int M) {
    constexpr int NTW = NT / 4;
    constexpr int NTILES = NTW / 8;
    __shared__ ushort_t As[2][128][40];
    __shared__ ushort_t Bs[2][NT][40];
    const int tid = threadIdx.x;
    const int wid = tid >> 5, lane = tid & 31;
    const int wm = wid >> 2, wn = wid & 3;
    const int m0 = bx * 128;
    const int nb = by * 128;

    float d[4][NTILES][4];
    #pragma unroll
    for (int mt = 0; mt < 4; mt++)
        #pragma unroll
        for (int nt = 0; nt < NTILES; nt++)
            #pragma unroll
            for (int j = 0; j < 4; j++) d[mt][nt][j] = 0.f;

    #pragma unroll 1
    for (int k0 = 0; k0 < 128; k0 += 32) {
        // A tile: fp32 load, split to bf16 hi/lo in registers, store to SMEM
        #pragma unroll
        for (int l = 0; l < 4; l++) {
            int i = tid + l * 256;
            int r = i >> 3, cq = (i & 7) * 4;
            float4 v = make_float4(0.f, 0.f, 0.f, 0.f);
            if (m0 + r < M) v = *(const float4*)&A[(size_t)(m0 + r) * 128 + k0 + cq];
            ushort4 h4, l4;
            split_bf16(v.x, h4.x, l4.x); split_bf16(v.y, h4.y, l4.y);
            split_bf16(v.z, h4.z, l4.z); split_bf16(v.w, h4.w, l4.w);
            *(ushort4*)&As[0][r][cq] = h4;
            *(ushort4*)&As[1][r][cq] = l4;
        }
        #pragma unroll
        for (int l = 0; l < (NT * 4) / 256; l++) {
            int i = tid + l * 256;
            int r = i >> 2, s = i & 3;
            *(uint4*)&Bs[0][r][s * 8] = *(const uint4*)&Bhi[(size_t)(nb + r) * 128 + k0 + s * 8];
            *(uint4*)&Bs[1][r][s * 8] = *(const uint4*)&Blo[(size_t)(nb + r) * 128 + k0 + s * 8];
        }
        __syncthreads();
        #pragma unroll
        for (int kk = 0; kk < 32; kk += 16) {
            uint32_t ah[4][4], al[4][4], bh[NTILES][2], bl[NTILES][2];
            #pragma unroll
            for (int mt = 0; mt < 4; mt++) {
                int ar = wm * 64 + mt * 16 + (lane & 15);
                int ac = kk + (lane >> 4) * 8;
                ldsm_x4(ah[mt], smem_u32(&As[0][ar][ac]));
                ldsm_x4(al[mt], smem_u32(&As[1][ar][ac]));
            }
            #pragma unroll
            for (int nt = 0; nt < NTILES; nt++) {
                int l16 = lane & 15;
                int br = wn * NTW + nt * 8 + (l16 & 7);
                int bc = kk + (l16 >> 3) * 8;
                ldsm_x2(bh[nt], smem_u32(&Bs[0][br][bc]));
                ldsm_x2(bl[nt], smem_u32(&Bs[1][br][bc]));
            }
            #pragma unroll
            for (int mt = 0; mt < 4; mt++)
                #pragma unroll
                for (int nt = 0; nt < NTILES; nt++) {
                    mma16816(d[mt][nt], ah[mt], bh[nt]);
                    mma16816(d[mt][nt], al[mt], bh[nt]);
                    mma16816(d[mt][nt], ah[mt], bl[nt]);
                }
        }
        __syncthreads();
    }
    ushort_t* C = (NT == 64 || by == 0) ? C1h : C2h;
    const int cstride = (NT == 64) ? 64 : 128;
    #pragma unroll
    for (int mt = 0; mt < 4; mt++) {
        int r0 = m0 + wm * 64 + mt * 16 + (lane >> 2);
        #pragma unroll
        for (int nt = 0; nt < NTILES; nt++) {
            int c = wn * NTW + nt * 8 + (lane & 3) * 2;
            if (r0 < M)
                *reinterpret_cast<__half2*>(&C[(size_t)r0 * cstride + c]) =
                    __floats2half2_rn(d[mt][nt][0], d[mt][nt][1]);
            if (r0 + 8 < M)
                *reinterpret_cast<__half2*>(&C[(size_t)(r0 + 8) * cstride + c]) =
                    __floats2half2_rn(d[mt][nt][2], d[mt][nt][3]);
        }
    }
}

// ---------------- standalone GEMM kernels ----------------
template<int NT>
__global__ void __launch_bounds__(256) mmagemm_kernel(
        const float* __restrict__ A,
        const ushort_t* __restrict__ Bhi, const ushort_t* __restrict__ Blo,
        ushort_t* __restrict__ C1h, ushort_t* __restrict__ C2h, int M) {
    gemm_body<NT>(blockIdx.x, blockIdx.y, A, Bhi, Blo, C1h, C2h, M);
}

// ---------------- K1: weight prep + compose + zero counters ----------------
__global__ void __launch_bounds__(256) prep_all_kernel(
        const float* __restrict__ Ws0, const float* __restrict__ as0,
        const float* __restrict__ Wd0, const float* __restrict__ ad0,
        const float* __restrict__ Lw0,
        const float* __restrict__ Ws1, const float* __restrict__ as1,
        const float* __restrict__ Wd1, const float* __restrict__ ad1,
        const float* __restrict__ Lw1,
        const float* __restrict__ Wts, const float* __restrict__ ats,
        const float* __restrict__ Wtd, const float* __restrict__ atd) {
    int blk = blockIdx.x;
    int t = threadIdx.x;
    if (blk < 288) {
        int idx = blk * 256 + t;
        ushort_t *ih, *il;
        int n, k;
        float v;
        if (idx < 32768) {
            n = idx >> 7; k = idx & 127;
            v = (n < 128) ? Ws0[k * 128 + n] : Lw0[k * 128 + (n - 128)];
            ih = g_wb0hi; il = g_wb0lo;
        } else if (idx < 65536) {
            int e = idx - 32768;
            n = e >> 7; k = e & 127;
            v = (n < 128) ? Ws1[k * 128 + n] : Lw1[k * 128 + (n - 128)];
            ih = g_wb1hi; il = g_wb1lo;
        } else {
            int e = idx - 65536;
            n = e >> 7; k = e & 127;
            v = Wts[k * 64 + n];
            ih = g_wbthi; il = g_wbtlo;
        }
        ushort_t h, l;
        split_bf16(v, h, l);
        ih[n * 128 + k] = h;
        il[n * 128 + k] = l;
    } else if (blk < 291) {
        int b = blk - 288;
        if (b == 0) {
            if (t < 128) {
                float s = 0.f;
                for (int n = 0; n < 128; n++) s += Ws0[t * 128 + n] * as0[n];
                g_wc[t] = s;
            } else {
                int i = t - 128; float s = 0.f;
                for (int n = 0; n < 128; n++) s += Wd0[i * 128 + n] * ad0[n];
                g_wc[128 + i] = s;
            }
        } else if (b == 1) {
            if (t < 128) {
                float s = 0.f;
                for (int n = 0; n < 128; n++) s += Ws1[t * 128 + n] * as1[n];
                g_wc[256 + t] = s;
            } else {
                int i = t - 128; float s = 0.f;
                for (int n = 0; n < 128; n++) s += Wd1[i * 128 + n] * ad1[n];
                g_wc[384 + i] = s;
            }
        } else {
            if (t < 128) {
                float s = 0.f;
                for (int n = 0; n < 64; n++) s += Wts[t * 64 + n] * ats[n];
                g_wc[512 + t] = s;
            } else if (t < 192) {
                int i = t - 128; float s = 0.f;
                for (int n = 0; n < 64; n++) s += Wtd[i * 64 + n] * atd[n];
                g_wc[640 + i] = s;
            }
        }
    } else {
        int i = (blk - 291) * 256 + t;
        if (i < N_PANO) g_cnt[i] = 0;
        else if (i < N_PANO + N_FP) g_cnt_fp[i - N_PANO] = 0;
    }
}

// ---------------- K2: histogram + attention dot GEMVs ----------------
#define K2_HIST  EALL_BLKS                 // 3321
#define K2_GEMV2 (K2_HIST + 6250)          // 9571
#define K2_GEMV64 (K2_GEMV2 + 1250)        // 10821
__global__ void __launch_bounds__(256) hist_gemv_kernel(
        const int* __restrict__ dst_pp, const int* __restrict__ dst_pf,
        const float* __restrict__ X, const float* __restrict__ Xfp) {
    int blk = blockIdx.x;
    int t = threadIdx.x;
    if (blk < K2_HIST) {
        int i = blk * 256 + t;
        if (i < E_PP) atomicAdd(&g_cnt[dst_pp[i]], 1);
        else if (i < E_PP + E_PF) atomicAdd(&g_cnt_fp[dst_pf[i - E_PP]], 1);
    } else if (blk < K2_GEMV2) {
        int gw = ((blk - K2_HIST) * 256 + t) >> 5;
        int lane = t & 31;
        if (gw >= N_PANO) return;
        float4 x = *(const float4*)&X[(size_t)gw * 128 + lane * 4];
        float4 a = *(const float4*)&g_wc[0 + lane * 4];
        float4 b = *(const float4*)&g_wc[128 + lane * 4];
        float sa = x.x * a.x + x.y * a.y + x.z * a.z + x.w * a.w;
        float sb = x.x * b.x + x.y * b.y + x.z * b.z + x.w * b.w;
        #pragma unroll
        for (int o = 16; o; o >>= 1) {
            sa += __shfl_xor_sync(0xFFFFFFFFu, sa, o);
            sb += __shfl_xor_sync(0xFFFFFFFFu, sb, o);
        }
        if (lane == 0) { g_es[gw] = sa; g_ed[gw] = sb; }
    } else {
        int gw = ((blk - K2_GEMV2) * 256 + t) >> 5;
        int lane = t & 31;
        if (gw >= N_FP) return;
        float2 x = *(const float2*)&Xfp[(size_t)gw * 64 + lane * 2];
        float2 a = *(const float2*)&g_wc[640 + lane * 2];
        float s = x.x * a.x + x.y * a.y;
        #pragma unroll
        for (int o = 16; o; o >>= 1) s += __shfl_xor_sync(0xFFFFFFFFu, s, o);
        if (lane == 0) g_edfp[gw] = s;
    }
}

// ---- scan phase 1: per-block tile scan ----
__global__ void __launch_bounds__(256) scan1_kernel() {
    __shared__ int woff[9];
    int blk = blockIdx.x;
    bool fp = blk >= SCAN_BPP;
    const int N = fp ? N_FP : N_PANO;
    const int* cnt = fp ? g_cnt_fp : g_cnt;
    int* off = fp ? g_off_fp : g_off;
    int base = (fp ? blk - SCAN_BPP : blk) * 1024;
    int t = threadIdx.x;
    int lane = t & 31, wid = t >> 5;
    int idx = base + t * 4;
    int4 v = make_int4(0, 0, 0, 0);
    if (idx < N) v = *(const int4*)&cnt[idx];
    int s0 = v.x, s1 = v.x + v.y, s2 = s1 + v.z, tot = s2 + v.w;
    int inc = tot;
    #pragma unroll
    for (int o = 1; o < 32; o <<= 1) {
        int n = __shfl_up_sync(0xFFFFFFFFu, inc, o);
        if (lane >= o) inc += n;
    }
    if (lane == 31) woff[wid] = inc;
    __syncthreads();
    if (t == 0) {
        int run = 0;
        #pragma unroll
        for (int j = 0; j < 8; j++) { int x = woff[j]; woff[j] = run; run += x; }
        g_bsum[blk] = run;
    }
    __syncthreads();
    int exc = woff[wid] + inc - tot;
    if (idx < N)
        *(int4*)&off[idx] = make_int4(exc, exc + s0, exc + s1, exc + s2);
}

// ---- scan phase 2+3 fused: each block computes its own prefix of block sums ----
__global__ void __launch_bounds__(256) scan3_kernel() {
    __shared__ int s_bo;
    int blk = blockIdx.x;
    bool fp = blk >= SCAN_BPP;
    const int N = fp ? N_FP : N_PANO;
    int* off = fp ? g_off_fp : g_off;
    int* cur = fp ? g_cur_fp : g_cur;
    int seg0 = fp ? SCAN_BPP : 0;
    int seg1 = fp ? SCAN_BLKS : SCAN_BPP;
    int t = threadIdx.x;
    if (t == 0) {
        int bo = 0;
        for (int j = seg0; j < blk; j++) bo += g_bsum[j];
        s_bo = bo;
        if (blk == seg0) {
            int total = 0;
            for (int j = seg0; j < seg1; j++) total += g_bsum[j];
            off[N] = total;
        }
    }
    __syncthreads();
    int base = (fp ? blk - SCAN_BPP : blk) * 1024;
    int idx = base + t * 4;
    if (idx >= N) return;
    int bo = s_bo;
    int4 o = *(const int4*)&off[idx];
    o.x += bo; o.y += bo; o.z += bo; o.w += bo;
    *(int4*)&off[idx] = o;
    *(int4*)&cur[idx] = o;
}

// ---------------- K5: layer-0 GEMM fused with edge scatter ----------------
__global__ void __launch_bounds__(256) gemm0_scatter_kernel(
        const float* __restrict__ A,
        const ushort_t* __restrict__ Bhi, const ushort_t* __restrict__ Blo,
        ushort_t* __restrict__ C1h, ushort_t* __restrict__ C2h,
        const int* __restrict__ src_pp, const int* __restrict__ dst_pp,
        const int* __restrict__ src_pf, const int* __restrict__ dst_pf) {
    int blk = blockIdx.x;
    if (blk < 2 * GEMM_MBLKS) {
        gemm_body<128>(blk % GEMM_MBLKS, blk / GEMM_MBLKS, A, Bhi, Blo, C1h, C2h, N_PANO);
    } else {
        int i = (blk - 2 * GEMM_MBLKS) * 256 + threadIdx.x;
        if (i < E_PP) {
            int pos = atomicAdd(&g_cur[dst_pp[i]], 1);
            g_srt[pos] = src_pp[i];
        } else if (i < E_PP + E_PF) {
            int j = i - E_PP;
            int pos = atomicAdd(&g_cur_fp[dst_pf[j]], 1);
            g_srt_fp[pos] = src_pf[j];
        }
    }
}

// ---------------- CSR aggregation + finalize + next-stage dots ----------------
__global__ void __launch_bounds__(256) agg_pp_kernel(const float* __restrict__ b,
                                                     const float* __restrict__ Lb,
                                                     const float* __restrict__ es_in,
                                                     const float* __restrict__ ed_in,
                                                     const float* __restrict__ wa,
                                                     const float* __restrict__ wb,
                                                     float* __restrict__ ea,
                                                     float* __restrict__ eb) {
    int gw = (blockIdx.x * blockDim.x + threadIdx.x) >> 5;
    int lane = threadIdx.x & 31;
    if (gw >= N_PANO) return;
    int start = g_off[gw];
    int end   = g_off[gw + 1];
    float edd = ed_in[gw];
    float4 acc = make_float4(0.f, 0.f, 0.f, 0.f);
    float exsum = 0.f;
    for (int base = start; base < end; base += 32) {
        int m = end - base; if (m > 32) m = 32;
        int s = 0; float ex = 0.f;
        if (lane < m) {
            s = g_srt[base + lane];
            float ez = es_in[s] + edd;
            float e = ez > 0.f ? ez : 0.2f * ez;
            ex = __expf(e);
        }
        exsum += ex;
        for (int j = 0; j < m; j++) {
            int sj   = __shfl_sync(0xFFFFFFFFu, s, j);
            float xj = __shfl_sync(0xFFFFFFFFu, ex, j);
            uint2 hp = *(const uint2*)&g_hsh[(size_t)sj * 128 + lane * 4];
            float2 f0 = __half22float2(*reinterpret_cast<const __half2*>(&hp.x));
            float2 f1 = __half22float2(*reinterpret_cast<const __half2*>(&hp.y));
            acc.x += f0.x * xj; acc.y += f0.y * xj;
            acc.z += f1.x * xj; acc.w += f1.y * xj;
        }
    }
    #pragma unroll
    for (int o = 16; o; o >>= 1) exsum += __shfl_xor_sync(0xFFFFFFFFu, exsum, o);
    float inv = exsum > 0.f ? 1.f / exsum : 0.f;
    uint2 lp = *(const uint2*)&g_linh[(size_t)gw * 128 + lane * 4];
    float2 l0 = __half22float2(*reinterpret_cast<const __half2*>(&lp.x));
    float2 l1 = __half22float2(*reinterpret_cast<const __half2*>(&lp.y));
    float4 bb = *(const float4*)&b[lane * 4];
    float4 lb = *(const float4*)&Lb[lane * 4];
    float4 r;
    r.x = fmaxf(acc.x * inv + bb.x + l0.x + lb.x, 0.f);
    r.y = fmaxf(acc.y * inv + bb.y + l0.y + lb.y, 0.f);
    r.z = fmaxf(acc.z * inv + bb.z + l1.x + lb.z, 0.f);
    r.w = fmaxf(acc.w * inv + bb.w + l1.y + lb.w, 0.f);
    *(float4*)&g_h[(size_t)gw * 128 + lane * 4] = r;
    float4 a4 = *(const float4*)&wa[lane * 4];
    float sa = r.x * a4.x + r.y * a4.y + r.z * a4.z + r.w * a4.w;
    float sb = 0.f;
    if (eb) {
        float4 b4 = *(const float4*)&wb[lane * 4];
        sb = r.x * b4.x + r.y * b4.y + r.z * b4.z + r.w * b4.w;
    }
    #pragma unroll
    for (int o = 16; o; o >>= 1) {
        sa += __shfl_xor_sync(0xFFFFFFFFu, sa, o);
        sb += __shfl_xor_sync(0xFFFFFFFFu, sb, o);
    }
    if (lane == 0) {
        ea[gw] = sa;
        if (eb) eb[gw] = sb;
    }
}

__global__ void __launch_bounds__(256) agg_pf_kernel(const float* __restrict__ bt,
                                                     float* __restrict__ out) {
    int gw = (blockIdx.x * blockDim.x + threadIdx.x) >> 5;
    int lane = threadIdx.x & 31;
    if (gw >= N_FP) return;
    int start = g_off_fp[gw];
    int end   = g_off_fp[gw + 1];
    float edd = g_edfp[gw];
    float2 acc = make_float2(0.f, 0.f);
    float exsum = 0.f;
    for (int base = start; base < end; base += 32) {
        int m = end - base; if (m > 32) m = 32;
        int s = 0; float ex = 0.f;
        if (lane < m) {
            s = g_srt_fp[base + lane];
            float ez = g_es3[s] + edd;
            float e = ez > 0.f ? ez : 0.2f * ez;
            ex = __expf(e);
        }
        exsum += ex;
        for (int j = 0; j < m; j++) {
            int sj   = __shfl_sync(0xFFFFFFFFu, s, j);
            float xj = __shfl_sync(0xFFFFFFFFu, ex, j);
            uint32_t hp = *(const uint32_t*)&g_hsh[(size_t)sj * 64 + lane * 2];
            float2 f = __half22float2(*reinterpret_cast<const __half2*>(&hp));
            acc.x += f.x * xj; acc.y += f.y * xj;
        }
    }
    #pragma unroll
    for (int o = 16; o; o >>= 1) exsum += __shfl_xor_sync(0xFFFFFFFFu, exsum, o);
    float inv = exsum > 0.f ? 1.f / exsum : 0.f;
    float2 bb = *(const float2*)&bt[lane * 2];
    *(float2*)&out[(size_t)gw * 64 + lane * 2] = make_float2(acc.x * inv + bb.x,
                                                             acc.y * inv + bb.y);
}

// ---------------- launch ----------------
extern "C" void kernel_launch(void* const* d_in, const int* in_sizes, int n_in,
                              void* d_out, int out_size) {
    const float* x_pano = (const float*)d_in[0];
    const float* x_fp   = (const float*)d_in[1];
    const float* Ws0 = (const float*)d_in[2];
    const float* Wd0 = (const float*)d_in[3];
    const float* as0 = (const float*)d_in[4];
    const float* ad0 = (const float*)d_in[5];
    const float* b0  = (const float*)d_in[6];
    const float* Lw0 = (const float*)d_in[7];
    const float* Lb0 = (const float*)d_in[8];
    const float* Ws1 = (const float*)d_in[9];
    const float* Wd1 = (const float*)d_in[10];
    const float* as1 = (const float*)d_in[11];
    const float* ad1 = (const float*)d_in[12];
    const float* b1  = (const float*)d_in[13];
    const float* Lw1 = (const float*)d_in[14];
    const float* Lb1 = (const float*)d_in[15];
    const float* Wts = (const float*)d_in[16];
    const float* Wtd = (const float*)d_in[17];
    const float* ats = (const float*)d_in[18];
    const float* atd = (const float*)d_in[19];
    const float* bt  = (const float*)d_in[20];
    const int* edge_pp = (const int*)d_in[21];
    const int* pf_src  = (const int*)d_in[22];
    const int* pf_dst  = (const int*)d_in[23];
    const int* pp_src = edge_pp;
    const int* pp_dst = edge_pp + E_PP;

    float *p_h, *p_es, *p_ed, *p_es2, *p_ed2, *p_es3, *p_wc;
    cudaGetSymbolAddress((void**)&p_h,    g_h);
    cudaGetSymbolAddress((void**)&p_es,   g_es);
    cudaGetSymbolAddress((void**)&p_ed,   g_ed);
    cudaGetSymbolAddress((void**)&p_es2,  g_es2);
    cudaGetSymbolAddress((void**)&p_ed2,  g_ed2);
    cudaGetSymbolAddress((void**)&p_es3,  g_es3);
    cudaGetSymbolAddress((void**)&p_wc,   g_wc);
    ushort_t *p_hsh, *p_linh, *p_b0hi, *p_b0lo, *p_b1hi, *p_b1lo, *p_bthi, *p_btlo;
    cudaGetSymbolAddress((void**)&p_hsh,  g_hsh);
    cudaGetSymbolAddress((void**)&p_linh, g_linh);
    cudaGetSymbolAddress((void**)&p_b0hi, g_wb0hi);
    cudaGetSymbolAddress((void**)&p_b0lo, g_wb0lo);
    cudaGetSymbolAddress((void**)&p_b1hi, g_wb1hi);
    cudaGetSymbolAddress((void**)&p_b1lo, g_wb1lo);
    cudaGetSymbolAddress((void**)&p_bthi, g_wbthi);
    cudaGetSymbolAddress((void**)&p_btlo, g_wbtlo);

    // K1: weight prep + compose + zero counters
    prep_all_kernel<<<526, 256>>>(Ws0, as0, Wd0, ad0, Lw0,
                                  Ws1, as1, Wd1, ad1, Lw1,
                                  Wts, ats, Wtd, atd);
    // K2: histogram + attention dots (layer-0 + fp side)
    hist_gemv_kernel<<<K2_GEMV64, 256>>>(pp_dst, pf_dst, x_pano, x_fp);
    // K3/K4: scan
    scan1_kernel<<<SCAN_BLKS, 256>>>();
    scan3_kernel<<<SCAN_BLKS, 256>>>();
    // K5: layer-0 GEMM + edge scatter (overlapped)
    gemm0_scatter_kernel<<<2 * GEMM_MBLKS + EALL_BLKS, 256>>>(
        x_pano, p_b0hi, p_b0lo, p_hsh, p_linh,
        pp_src, pp_dst, pf_src, pf_dst);
    // layer 0 aggregation
    agg_pp_kernel<<<6250, 256>>>(b0, Lb0, p_es, p_ed, p_wc + 256, p_wc + 384, p_es2, p_ed2);
    // layer 1
    mmagemm_kernel<128><<<dim3(GEMM_MBLKS, 2), 256>>>(p_h, p_b1hi, p_b1lo, p_hsh, p_linh, N_PANO);
    agg_pp_kernel<<<6250, 256>>>(b1, Lb1, p_es2, p_ed2, p_wc + 512, (const float*)0,
                                 p_es3, (float*)0);
    // translate
    mmagemm_kernel<64><<<dim3(GEMM_MBLKS, 1), 256>>>(p_h, p_bthi, p_btlo, p_hsh, (ushort_t*)0, N_PANO);
    agg_pf_kernel<<<1250, 256>>>(bt, (float*)d_out);
}